// round 11
// baseline (speedup 1.0000x reference)
#include <cuda_runtime.h>
#include <cuda_bf16.h>
#include <math.h>
#include <stdint.h>

// ---------------------------------------------------------------------------
// RelationNetworks forward. B=1024, C=64, L=64, H=64, IMG=27.
// conv chain: 27 ->(s1) 25 ->(s1) 23 ->(s2) 11 ->(s2) 5
// Activations NHWC. conv2/3/4 via mma.sync m16n8k16 bf16, 2-term hi/lo split,
// 3-pass product, fp32 accum. BN+ReLU+split hoisted into convert_kernel
// (applied ONCE per element instead of 9x in the conv gather).
// ---------------------------------------------------------------------------

__device__ float d_buf1[1024 * 625 * 64];
__device__ float d_buf2[1024 * 529 * 64];
__device__ float d_buf3[1024 * 121 * 64];
__device__ float d_buf4[1024 * 25 * 64];
__device__ uint32_t d_bh1[1024 * 625 * 32], d_bl1[1024 * 625 * 32];
__device__ uint32_t d_bh2[1024 * 529 * 32], d_bl2[1024 * 529 * 32];
__device__ uint32_t d_bh3[1024 * 121 * 32], d_bl3[1024 * 121 * 32];
__device__ float d_Wt1[32 * 64];          // conv1 [k pad32][oc]
// fragment-major packed bf16 weights:
// idx = (ch*2+wn)*256 + nf*64 + step*32 + lane -> {b0h, b1h, b0l, b1l}
__device__ uint4 d_Wf2[9216];
__device__ uint4 d_Wf3[9216];
__device__ uint4 d_Wf4[9216];
__device__ float d_statsA[8 * 128];
__device__ float d_Ssum[2];
__device__ float d_g0[1024 * 64];
__device__ float d_g1[1024 * 64];

// ---------------------------- helpers --------------------------------------
__device__ __forceinline__ uint16_t f2bf(float x, float& lo) {
    __nv_bfloat16 h = __float2bfloat16_rn(x);
    lo = x - __bfloat162float(h);
    return *(uint16_t*)&h;
}

__device__ __forceinline__ void mma_bf16(float c[4], const uint32_t a[4],
                                         uint32_t b0, uint32_t b1) {
    asm volatile(
        "mma.sync.aligned.m16n8k16.row.col.f32.bf16.bf16.f32 "
        "{%0,%1,%2,%3}, {%4,%5,%6,%7}, {%8,%9}, {%0,%1,%2,%3};"
        : "+f"(c[0]), "+f"(c[1]), "+f"(c[2]), "+f"(c[3])
        : "r"(a[0]), "r"(a[1]), "r"(a[2]), "r"(a[3]), "r"(b0), "r"(b1));
}

// ---------------------------- small kernels --------------------------------
__global__ void zero_misc_kernel() {
    int t = threadIdx.x;
    if (t < 1024) d_statsA[t] = 0.f;
    if (t < 2) d_Ssum[t] = 0.f;
}

__global__ void prep_weights_kernel(const float* __restrict__ Wc1,
                                    const float* __restrict__ Wc2,
                                    const float* __restrict__ Wc3,
                                    const float* __restrict__ Wc4) {
    int i = blockIdx.x * blockDim.x + threadIdx.x;
    if (i < 32 * 64) {
        int k = i >> 6, oc = i & 63;
        d_Wt1[i] = (k < 27) ? Wc1[oc * 27 + (k % 3) * 9 + (k / 3)] : 0.f;
    }
    if (i < 9216) {
        int lane = i & 31;
        int step = (i >> 5) & 1;
        int nf = (i >> 6) & 3;
        int wn = (i >> 8) & 1;
        int ch = i >> 9;                       // 0..17
        int n = wn * 32 + nf * 8 + (lane >> 2);
        int lt = lane & 3;
        int kb = ch * 32 + step * 16;
        int ks[4] = {kb + 2 * lt, kb + 2 * lt + 1, kb + 2 * lt + 8, kb + 2 * lt + 9};
        const float* Ws[3] = {Wc2, Wc3, Wc4};
        uint4* Wd[3] = {d_Wf2, d_Wf3, d_Wf4};
#pragma unroll
        for (int L = 0; L < 3; L++) {
            uint16_t h[4];
            float lo[4];
#pragma unroll
            for (int e = 0; e < 4; e++) {
                int k = ks[e];
                float v = Ws[L][n * 576 + (k & 63) * 9 + (k >> 6)];
                h[e] = f2bf(v, lo[e]);
            }
            uint16_t l0 = f2bf(lo[0], lo[0]), l1 = f2bf(lo[1], lo[1]);
            uint16_t l2 = f2bf(lo[2], lo[2]), l3 = f2bf(lo[3], lo[3]);
            Wd[L][i] = make_uint4(((uint32_t)h[1] << 16) | h[0],
                                  ((uint32_t)h[3] << 16) | h[2],
                                  ((uint32_t)l1 << 16) | l0,
                                  ((uint32_t)l3 << 16) | l2);
        }
    }
}

__global__ void att_sum_kernel(const float* __restrict__ lat) {
    int i = blockIdx.x * blockDim.x + threadIdx.x;
    float p0 = 0.f, p1 = 0.f;
    for (int idx = i; idx < 65536; idx += gridDim.x * blockDim.x) {
        int b = idx >> 6, c = idx & 63;
        p0 += expf(lat[(b * 4 + 2) * 64 + c]);
        p1 += expf(lat[(b * 4 + 3) * 64 + c]);
    }
#pragma unroll
    for (int o = 16; o; o >>= 1) {
        p0 += __shfl_down_sync(0xffffffffu, p0, o);
        p1 += __shfl_down_sync(0xffffffffu, p1, o);
    }
    if ((threadIdx.x & 31) == 0) {
        atomicAdd(&d_Ssum[0], p0);
        atomicAdd(&d_Ssum[1], p1);
    }
}

// ---- BN+ReLU+bf16 hi/lo split, once per element ---------------------------
// out: packed bf16x2 NHWC [row][c2 0..31] hi and lo.
__global__ void __launch_bounds__(256) convert_kernel(
    const float* __restrict__ buf, int rows,
    const float* __restrict__ stats, const float* __restrict__ bn_g,
    const float* __restrict__ bn_b, float invN,
    uint32_t* __restrict__ bh, uint32_t* __restrict__ bl) {
    __shared__ float sBn[128];
    if (threadIdx.x < 64) {
        int c = threadIdx.x;
        float s = stats[c], q = stats[64 + c];
        float mean = s * invN;
        float var = q * invN - mean * mean;
        float sc = bn_g[c] * rsqrtf(var + 1e-5f);
        sBn[c] = sc;
        sBn[64 + c] = bn_b[c] - mean * sc;
    }
    __syncthreads();
    int total = rows * 2;
    for (int t = blockIdx.x * blockDim.x + threadIdx.x; t < total;
         t += gridDim.x * blockDim.x) {
        int r = t >> 1, hf = (t & 1) * 32;
        const float* src = buf + (size_t)r * 64 + hf;
        uint32_t oh[16], ol[16];
#pragma unroll
        for (int j = 0; j < 8; j++) {
            float4 v = *(const float4*)(src + j * 4);
            int c = hf + j * 4;
            float4 sc = *(const float4*)&sBn[c];
            float4 sh = *(const float4*)&sBn[64 + c];
            float x0 = fmaxf(fmaf(v.x, sc.x, sh.x), 0.f);
            float x1 = fmaxf(fmaf(v.y, sc.y, sh.y), 0.f);
            float x2 = fmaxf(fmaf(v.z, sc.z, sh.z), 0.f);
            float x3 = fmaxf(fmaf(v.w, sc.w, sh.w), 0.f);
            float r0, r1, r2, r3;
            uint16_t h0 = f2bf(x0, r0), h1 = f2bf(x1, r1);
            uint16_t h2 = f2bf(x2, r2), h3 = f2bf(x3, r3);
            uint16_t l0 = f2bf(r0, r0), l1 = f2bf(r1, r1);
            uint16_t l2 = f2bf(r2, r2), l3 = f2bf(r3, r3);
            oh[j * 2] = ((uint32_t)h1 << 16) | h0;
            oh[j * 2 + 1] = ((uint32_t)h3 << 16) | h2;
            ol[j * 2] = ((uint32_t)l1 << 16) | l0;
            ol[j * 2 + 1] = ((uint32_t)l3 << 16) | l2;
        }
        uint32_t* dh = bh + (size_t)r * 32 + (hf >> 1);
        uint32_t* dl = bl + (size_t)r * 32 + (hf >> 1);
#pragma unroll
        for (int j = 0; j < 4; j++) {
            *(uint4*)(dh + j * 4) =
                make_uint4(oh[j * 4], oh[j * 4 + 1], oh[j * 4 + 2], oh[j * 4 + 3]);
            *(uint4*)(dl + j * 4) =
                make_uint4(ol[j * 4], ol[j * 4 + 1], ol[j * 4 + 2], ol[j * 4 + 3]);
        }
    }
}

// ---- conv1: NCHW input (3 ch), NHWC raw output + shuffle-reduced stats ----
__global__ void __launch_bounds__(256) conv1_kernel(
    const float* __restrict__ in, const float* __restrict__ Wt,
    float* __restrict__ out, float* __restrict__ slot) {
    constexpr int BK = 16;
    __shared__ float As[BK][64];
    __shared__ float Bs[BK][64];
    __shared__ float sred[2][64][8];

    const int tid = threadIdx.x;
    const int lane = tid & 31, warp = tid >> 5;
    const int tx = tid & 15, ty = tid >> 4;
    const int m0 = blockIdx.x * 64;

    const int mi = tid >> 2;
    const int kb = (tid & 3) * 4;
    const int mg = m0 + mi;
    const int bI = mg / 625;
    const int sp = mg - bI * 625;
    const int oy = sp / 25;
    const int ox = sp - oy * 25;
    const float* inb = in + ((size_t)bI * 3) * 729 + oy * 27 + ox;

    float acc[4][4];
#pragma unroll
    for (int i = 0; i < 4; i++)
#pragma unroll
        for (int j = 0; j < 4; j++) acc[i][j] = 0.f;

    for (int k0 = 0; k0 < 32; k0 += BK) {
        {
            int ki = tid >> 4;
            int oc = (tid & 15) * 4;
            *(float4*)&Bs[ki][oc] = *(const float4*)(Wt + (k0 + ki) * 64 + oc);
        }
#pragma unroll
        for (int j = 0; j < 4; j++) {
            int k = k0 + kb + j;
            float v = 0.f;
            if (k < 27) {
                int w = k / 3, ic = k - w * 3;
                int ky = w / 3, kx = w - ky * 3;
                v = inb[ic * 729 + ky * 27 + kx];
            }
            As[kb + j][mi] = v;
        }
        __syncthreads();
#pragma unroll
        for (int kk = 0; kk < BK; kk++) {
            float4 a4 = *(float4*)&As[kk][ty * 4];
            float4 b4 = *(float4*)&Bs[kk][tx * 4];
            float av[4] = {a4.x, a4.y, a4.z, a4.w};
            float bw[4] = {b4.x, b4.y, b4.z, b4.w};
#pragma unroll
            for (int i = 0; i < 4; i++)
#pragma unroll
                for (int j = 0; j < 4; j++)
                    acc[i][j] = fmaf(av[i], bw[j], acc[i][j]);
        }
        __syncthreads();
    }
    // shuffle-reduced stats: combine the warp's two ty rows via shfl 16
#pragma unroll
    for (int j = 0; j < 4; j++) {
        float s = 0.f, q = 0.f;
#pragma unroll
        for (int i = 0; i < 4; i++) {
            float v = acc[i][j];
            s += v;
            q += v * v;
        }
        s += __shfl_down_sync(0xffffffffu, s, 16);
        q += __shfl_down_sync(0xffffffffu, q, 16);
        if (lane < 16) {
            sred[0][lane * 4 + j][warp] = s;
            sred[1][lane * 4 + j][warp] = q;
        }
    }
#pragma unroll
    for (int i = 0; i < 4; i++) {
        float4 v = make_float4(acc[i][0], acc[i][1], acc[i][2], acc[i][3]);
        *(float4*)(out + (size_t)(m0 + ty * 4 + i) * 64 + tx * 4) = v;
    }
    __syncthreads();
    if (tid < 128) {
        int s = tid >> 6, c = tid & 63;
        float v = 0.f;
#pragma unroll
        for (int w = 0; w < 8; w++) v += sred[s][c][w];
        atomicAdd(&slot[s * 64 + c], v);
    }
}

// ---- conv64 via mma.sync bf16 hi/lo (3-pass): BM=128, BN=64, BK=32 --------
// Inputs pre-converted packed bf16x2 hi/lo NHWC. Fused output stats.
template <int IH, int IW, int OH, int OW, int STRIDE>
__global__ void __launch_bounds__(256) conv_mma3_kernel(
    const uint32_t* __restrict__ inh, const uint32_t* __restrict__ inl,
    const uint4* __restrict__ Wf, float* __restrict__ out,
    float* __restrict__ slot) {
    constexpr int OSP = OH * OW;
    constexpr int STG = 4352;                 // u32 per stage (hi 2176 + lo 2176)
    extern __shared__ uint32_t smu[];
    __shared__ float sred[2][64][8];

    const int tid = threadIdx.x;
    const int lane = tid & 31, warp = tid >> 5;
    const int wm = warp & 3, wn = warp >> 2;
    const int lg = lane >> 2, lt = lane & 3;

    // producer coords: one row per 2 threads, 16 k (8 k-pairs) each
    const int row = tid >> 1;
    const int khalf = tid & 1;
    const int mg = blockIdx.x * 128 + row;
    const int bI = mg / OSP;
    const int sp = mg - bI * OSP;
    const int oy = sp / OW;
    const int ox = sp - oy * OW;
    const size_t ibase = (((size_t)bI * IH + oy * STRIDE) * IW + ox * STRIDE) * 32;
    const uint32_t* inhp = inh + ibase;
    const uint32_t* inlp = inl + ibase;

    float c[2][4][4];
#pragma unroll
    for (int m = 0; m < 2; m++)
#pragma unroll
        for (int n = 0; n < 4; n++)
#pragma unroll
            for (int e = 0; e < 4; e++) c[m][n][e] = 0.f;

    // fill chunk ch into stage s: pure copy of packed bf16x2 words
    auto fill = [&](int s, int ch) {
        const int w = ch >> 1;
        const int c2b = (ch & 1) * 16 + khalf * 8;
        const int ky = w / 3, kx = w - ky * 3;
        uint32_t* aH = smu + s * STG;
        uint32_t* aL = aH + 2176;
        const uint32_t* sh_ = inhp + (ky * IW + kx) * 32 + c2b;
        const uint32_t* sl_ = inlp + (ky * IW + kx) * 32 + c2b;
        uint4 h0 = *(const uint4*)sh_, h1 = *(const uint4*)(sh_ + 4);
        uint4 l0 = *(const uint4*)sl_, l1 = *(const uint4*)(sl_ + 4);
        const int base = khalf * 8;
        aH[(base + 0) * 136 + row] = h0.x;
        aH[(base + 1) * 136 + row] = h0.y;
        aH[(base + 2) * 136 + row] = h0.z;
        aH[(base + 3) * 136 + row] = h0.w;
        aH[(base + 4) * 136 + row] = h1.x;
        aH[(base + 5) * 136 + row] = h1.y;
        aH[(base + 6) * 136 + row] = h1.z;
        aH[(base + 7) * 136 + row] = h1.w;
        aL[(base + 0) * 136 + row] = l0.x;
        aL[(base + 1) * 136 + row] = l0.y;
        aL[(base + 2) * 136 + row] = l0.z;
        aL[(base + 3) * 136 + row] = l0.w;
        aL[(base + 4) * 136 + row] = l1.x;
        aL[(base + 5) * 136 + row] = l1.y;
        aL[(base + 6) * 136 + row] = l1.z;
        aL[(base + 7) * 136 + row] = l1.w;
    };

    fill(0, 0);
    __syncthreads();

#pragma unroll 1
    for (int ch = 0; ch < 18; ch++) {
        if (ch + 1 < 18) fill((ch + 1) & 1, ch + 1);

        const uint32_t* aH = smu + (ch & 1) * STG;
        const uint32_t* aL = aH + 2176;
        const uint4* wp = Wf + (size_t)(ch * 2 + wn) * 256 + lane;
#pragma unroll
        for (int step = 0; step < 2; step++) {
            uint32_t ah[2][4], al[2][4];
#pragma unroll
            for (int m = 0; m < 2; m++) {
                int rf = wm * 32 + m * 16 + lg;
                int k2 = step * 8 + lt;
                ah[m][0] = aH[k2 * 136 + rf];
                ah[m][1] = aH[k2 * 136 + rf + 8];
                ah[m][2] = aH[(k2 + 4) * 136 + rf];
                ah[m][3] = aH[(k2 + 4) * 136 + rf + 8];
                al[m][0] = aL[k2 * 136 + rf];
                al[m][1] = aL[k2 * 136 + rf + 8];
                al[m][2] = aL[(k2 + 4) * 136 + rf];
                al[m][3] = aL[(k2 + 4) * 136 + rf + 8];
            }
#pragma unroll
            for (int nf = 0; nf < 4; nf++) {
                uint4 b = wp[nf * 64 + step * 32];
#pragma unroll
                for (int m = 0; m < 2; m++) {
                    mma_bf16(c[m][nf], ah[m], b.x, b.y);   // hi*hi
                    mma_bf16(c[m][nf], ah[m], b.z, b.w);   // hi*lo
                    mma_bf16(c[m][nf], al[m], b.x, b.y);   // lo*hi
                }
            }
        }
        __syncthreads();
    }

    // fused stats: per-col partials, stride-4 shuffle reduce, smem, atomics
#pragma unroll
    for (int nf = 0; nf < 4; nf++) {
#pragma unroll
        for (int e = 0; e < 2; e++) {
            float s = c[0][nf][e] + c[0][nf][e + 2] + c[1][nf][e] + c[1][nf][e + 2];
            float q = c[0][nf][e] * c[0][nf][e] + c[0][nf][e + 2] * c[0][nf][e + 2] +
                      c[1][nf][e] * c[1][nf][e] + c[1][nf][e + 2] * c[1][nf][e + 2];
#pragma unroll
            for (int o = 16; o >= 4; o >>= 1) {
                s += __shfl_down_sync(0xffffffffu, s, o);
                q += __shfl_down_sync(0xffffffffu, q, o);
            }
            if (lane < 4) {
                int col = wn * 32 + nf * 8 + lane * 2 + e;
                sred[0][col][warp] = s;
                sred[1][col][warp] = q;
            }
        }
    }

    // output stores
#pragma unroll
    for (int m = 0; m < 2; m++) {
        int r = blockIdx.x * 128 + wm * 32 + m * 16 + lg;
#pragma unroll
        for (int nf = 0; nf < 4; nf++) {
            int col = wn * 32 + nf * 8 + lt * 2;
            *(float2*)(out + (size_t)r * 64 + col) =
                make_float2(c[m][nf][0], c[m][nf][1]);
            *(float2*)(out + (size_t)(r + 8) * 64 + col) =
                make_float2(c[m][nf][2], c[m][nf][3]);
        }
    }
    __syncthreads();
    if (tid < 128) {
        int si = tid >> 6, col = tid & 63;
        int wbase = (col < 32) ? 0 : 4;
        float v = sred[si][col][wbase] + sred[si][col][wbase + 1] +
                  sred[si][col][wbase + 2] + sred[si][col][wbase + 3];
        atomicAdd(&slot[si * 64 + col], v);
    }
}

// ---- relation network: one block per batch element ------------------------
__global__ void __launch_bounds__(256) relation_kernel(
    const float* __restrict__ conv4, const float* __restrict__ lat,
    const float* __restrict__ Wg1, const float* __restrict__ bg1,
    const float* __restrict__ Wg2, const float* __restrict__ bg2,
    const float* __restrict__ Wg3, const float* __restrict__ bg3,
    const float* __restrict__ stats, const float* __restrict__ bn_g,
    const float* __restrict__ bn_b, float invN,
    int im, float* __restrict__ gout) {
    extern __shared__ float sm[];
    float* sW2 = sm;
    float* sW3 = sm + 4096;
    float* sTi = sm + 8192;
    float* sTj = sm + 9792;
    float* sCT = sm + 11392;
    float* sTw = sm + 13042;
    float* sH  = sm + 13108;
    float* sGp = sm + 15156;
    __shared__ float sBn[128];

    const int tid = threadIdx.x;
    const int b = blockIdx.x;
    const int lane = tid & 31, warp = tid >> 5;

    if (tid < 64) {
        float s = stats[tid], q = stats[64 + tid];
        float mean = s * invN;
        float var = q * invN - mean * mean;
        float sc = bn_g[tid] * rsqrtf(var + 1e-5f);
        sBn[tid] = sc;
        sBn[64 + tid] = bn_b[tid] - mean * sc;
    }
    for (int i = tid; i < 4096; i += 256) {
        sW2[i] = Wg2[i];
        sW3[i] = Wg3[i];
    }
    __syncthreads();

    const float invS = 1.f / (d_Ssum[im] + 1e-9f);
    const float* aRow = lat + ((size_t)b * 4 + 2 + im) * 64;
    const float* wRow = lat + ((size_t)b * 4 + im) * 64;

    for (int i = tid; i < 1600; i += 256) {
        int p = i >> 6, cc = i & 63;
        float v = conv4[((size_t)b * 25 + p) * 64 + cc];
        v = fmaxf(fmaf(v, sBn[cc], sBn[64 + cc]), 0.f);
        v *= expf(aRow[cc]) * invS;
        sCT[p * 66 + cc] = v;
    }
    if (tid < 50) {
        int p = tid % 25, cc = tid / 25;
        sCT[p * 66 + 64 + cc] = (cc == 0) ? (float)(p % 5) - 2.f : (float)(p / 5) - 2.f;
    }
    if (tid < 64) {
        float acc = bg1[tid];
        for (int cc = 0; cc < 64; cc++)
            acc = fmaf(wRow[cc], Wg1[(132 + cc) * 64 + tid], acc);
        sTw[tid] = acc;
    }
    __syncthreads();

    for (int o = tid; o < 1600; o += 256) {
        int p = o >> 6, h = o & 63;
        float aj = 0.f, ai = 0.f;
        for (int cc = 0; cc < 66; cc++) {
            float ctv = sCT[p * 66 + cc];
            aj = fmaf(ctv, Wg1[cc * 64 + h], aj);
            ai = fmaf(ctv, Wg1[(66 + cc) * 64 + h], ai);
        }
        sTj[p * 64 + h] = aj;
        sTi[p * 64 + h] = ai;
    }
    __syncthreads();

    const float twA = sTw[lane], twB = sTw[lane + 32];
    const float b2A = bg2[lane], b2B = bg2[lane + 32];
    const float b3A = bg3[lane], b3B = bg3[lane + 32];
    float gA = 0.f, gB = 0.f;
    float* hw = sH + warp * 256;

    for (int it = 0; it < 20; it++) {
        const int base = it * 32 + warp * 4;
#pragma unroll
        for (int s = 0; s < 4; s++) {
            int pr = base + s;
            bool vld = pr < 625;
            int p = vld ? pr / 25 : 0, qq = vld ? pr % 25 : 0;
            hw[lane * 4 + s] = fmaxf(sTi[p * 64 + lane] + sTj[qq * 64 + lane] + twA, 0.f);
            hw[(lane + 32) * 4 + s] =
                fmaxf(sTi[p * 64 + lane + 32] + sTj[qq * 64 + lane + 32] + twB, 0.f);
        }
        __syncwarp();

        float a0[4], a1[4];
#pragma unroll
        for (int s = 0; s < 4; s++) { a0[s] = b2A; a1[s] = b2B; }
#pragma unroll 8
        for (int k = 0; k < 64; k++) {
            float w0 = sW2[k * 64 + lane], w1 = sW2[k * 64 + lane + 32];
            float4 hv = *(float4*)&hw[k * 4];
            a0[0] = fmaf(hv.x, w0, a0[0]); a1[0] = fmaf(hv.x, w1, a1[0]);
            a0[1] = fmaf(hv.y, w0, a0[1]); a1[1] = fmaf(hv.y, w1, a1[1]);
            a0[2] = fmaf(hv.z, w0, a0[2]); a1[2] = fmaf(hv.z, w1, a1[2]);
            a0[3] = fmaf(hv.w, w0, a0[3]); a1[3] = fmaf(hv.w, w1, a1[3]);
        }
        __syncwarp();
#pragma unroll
        for (int s = 0; s < 4; s++) {
            hw[lane * 4 + s] = fmaxf(a0[s], 0.f);
            hw[(lane + 32) * 4 + s] = fmaxf(a1[s], 0.f);
        }
        __syncwarp();

#pragma unroll
        for (int s = 0; s < 4; s++) { a0[s] = b3A; a1[s] = b3B; }
#pragma unroll 8
        for (int k = 0; k < 64; k++) {
            float w0 = sW3[k * 64 + lane], w1 = sW3[k * 64 + lane + 32];
            float4 hv = *(float4*)&hw[k * 4];
            a0[0] = fmaf(hv.x, w0, a0[0]); a1[0] = fmaf(hv.x, w1, a1[0]);
            a0[1] = fmaf(hv.y, w0, a0[1]); a1[1] = fmaf(hv.y, w1, a1[1]);
            a0[2] = fmaf(hv.z, w0, a0[2]); a1[2] = fmaf(hv.z, w1, a1[2]);
            a0[3] = fmaf(hv.w, w0, a0[3]); a1[3] = fmaf(hv.w, w1, a1[3]);
        }
#pragma unroll
        for (int s = 0; s < 4; s++) {
            if (base + s < 625) {
                gA += fmaxf(a0[s], 0.f);
                gB += fmaxf(a1[s], 0.f);
            }
        }
        __syncwarp();
    }
    sGp[warp * 64 + lane] = gA;
    sGp[warp * 64 + lane + 32] = gB;
    __syncthreads();
    if (tid < 64) {
        float s = 0.f;
#pragma unroll
        for (int w = 0; w < 8; w++) s += sGp[w * 64 + tid];
        gout[(size_t)b * 64 + tid] = s;
    }
}

__global__ void final_head_kernel(const float* __restrict__ lat,
                                  const float* __restrict__ Wf1, const float* __restrict__ bf1,
                                  const float* __restrict__ Wf2, const float* __restrict__ bf2,
                                  const float* __restrict__ Wf3, const float* __restrict__ bf3,
                                  float* __restrict__ out) {
    __shared__ float sh1[8][64];
    int tid = threadIdx.x, lane = tid & 31, warp = tid >> 5;
    int b = blockIdx.x * 8 + warp;
    float a0 = bf1[lane], a1 = bf1[lane + 32];
    const float* g0 = d_g0 + (size_t)b * 64;
    const float* g1 = d_g1 + (size_t)b * 64;
    const float* lr = lat + (size_t)b * 256;
    for (int k = 0; k < 64; k++) {
        float g = g0[k];
        a0 = fmaf(g, Wf1[k * 64 + lane], a0);
        a1 = fmaf(g, Wf1[k * 64 + lane + 32], a1);
    }
    for (int k = 0; k < 64; k++) {
        float g = g1[k];
        a0 = fmaf(g, Wf1[(64 + k) * 64 + lane], a0);
        a1 = fmaf(g, Wf1[(64 + k) * 64 + lane + 32], a1);
    }
    for (int k = 0; k < 256; k++) {
        float g = lr[k];
        a0 = fmaf(g, Wf1[(128 + k) * 64 + lane], a0);
        a1 = fmaf(g, Wf1[(128 + k) * 64 + lane + 32], a1);
    }
    sh1[warp][lane] = fmaxf(a0, 0.f);
    sh1[warp][lane + 32] = fmaxf(a1, 0.f);
    __syncwarp();
    float c = bf2[lane];
    for (int k = 0; k < 64; k++) c = fmaf(sh1[warp][k], Wf2[k * 32 + lane], c);
    c = fmaxf(c, 0.f);
    float v = c * Wf3[lane];
#pragma unroll
    for (int o = 16; o; o >>= 1) v += __shfl_down_sync(0xffffffffu, v, o);
    if (lane == 0) out[b] = v + bf3[0];
}

extern "C" void kernel_launch(void* const* d_in, const int* in_sizes, int n_in,
                              void* d_out, int out_size) {
    const float* x0 = (const float*)d_in[0];
    const float* x1 = (const float*)d_in[1];
    const float* lat = (const float*)d_in[2];
    const float* Wc1 = (const float*)d_in[3];
    const float* Wc2 = (const float*)d_in[4];
    const float* Wc3 = (const float*)d_in[5];
    const float* Wc4 = (const float*)d_in[6];
    const float* bng = (const float*)d_in[7];
    const float* bnb = (const float*)d_in[8];
    const float* Wg1 = (const float*)d_in[9];
    const float* bg1 = (const float*)d_in[10];
    const float* Wg2 = (const float*)d_in[11];
    const float* bg2 = (const float*)d_in[12];
    const float* Wg3 = (const float*)d_in[13];
    const float* bg3 = (const float*)d_in[14];
    const float* Wf1 = (const float*)d_in[15];
    const float* bf1 = (const float*)d_in[16];
    const float* Wf2 = (const float*)d_in[17];
    const float* bf2 = (const float*)d_in[18];
    const float* Wf3 = (const float*)d_in[19];
    const float* bf3 = (const float*)d_in[20];
    float* out = (float*)d_out;

    float *buf1, *buf2, *buf3, *buf4, *wt1, *statsA, *g0p, *g1p;
    uint32_t *bh1, *bl1, *bh2, *bl2, *bh3, *bl3;
    uint4 *wf2, *wf3, *wf4;
    cudaGetSymbolAddress((void**)&buf1, d_buf1);
    cudaGetSymbolAddress((void**)&buf2, d_buf2);
    cudaGetSymbolAddress((void**)&buf3, d_buf3);
    cudaGetSymbolAddress((void**)&buf4, d_buf4);
    cudaGetSymbolAddress((void**)&bh1, d_bh1);
    cudaGetSymbolAddress((void**)&bl1, d_bl1);
    cudaGetSymbolAddress((void**)&bh2, d_bh2);
    cudaGetSymbolAddress((void**)&bl2, d_bl2);
    cudaGetSymbolAddress((void**)&bh3, d_bh3);
    cudaGetSymbolAddress((void**)&bl3, d_bl3);
    cudaGetSymbolAddress((void**)&wt1, d_Wt1);
    cudaGetSymbolAddress((void**)&wf2, d_Wf2);
    cudaGetSymbolAddress((void**)&wf3, d_Wf3);
    cudaGetSymbolAddress((void**)&wf4, d_Wf4);
    cudaGetSymbolAddress((void**)&statsA, d_statsA);
    cudaGetSymbolAddress((void**)&g0p, d_g0);
    cudaGetSymbolAddress((void**)&g1p, d_g1);

    const int REL_SMEM = 15668 * 4;
    cudaFuncSetAttribute(relation_kernel, cudaFuncAttributeMaxDynamicSharedMemorySize, REL_SMEM);
    const int MMA_SMEM = 2 * 4352 * 4;   // 34816 B
    cudaFuncSetAttribute(conv_mma3_kernel<25, 25, 23, 23, 1>,
                         cudaFuncAttributeMaxDynamicSharedMemorySize, MMA_SMEM);
    cudaFuncSetAttribute(conv_mma3_kernel<23, 23, 11, 11, 2>,
                         cudaFuncAttributeMaxDynamicSharedMemorySize, MMA_SMEM);
    cudaFuncSetAttribute(conv_mma3_kernel<11, 11, 5, 5, 2>,
                         cudaFuncAttributeMaxDynamicSharedMemorySize, MMA_SMEM);

    zero_misc_kernel<<<1, 1024>>>();
    prep_weights_kernel<<<36, 256>>>(Wc1, Wc2, Wc3, Wc4);
    att_sum_kernel<<<64, 512>>>(lat);

    for (int im = 0; im < 2; im++) {
        const float* x = im ? x1 : x0;
        float* gp = im ? g1p : g0p;
        float* sl = statsA + im * 4 * 128;

        conv1_kernel<<<10000, 256>>>(x, wt1, buf1, sl + 0 * 128);
        convert_kernel<<<1024, 256>>>(buf1, 640000, sl + 0 * 128, bng + 0,
                                      bnb + 0, 1.f / 640000.f, bh1, bl1);
        conv_mma3_kernel<25, 25, 23, 23, 1><<<4232, 256, MMA_SMEM>>>(
            bh1, bl1, wf2, buf2, sl + 1 * 128);
        convert_kernel<<<1024, 256>>>(buf2, 541696, sl + 1 * 128, bng + 64,
                                      bnb + 64, 1.f / 541696.f, bh2, bl2);
        conv_mma3_kernel<23, 23, 11, 11, 2><<<968, 256, MMA_SMEM>>>(
            bh2, bl2, wf3, buf3, sl + 2 * 128);
        convert_kernel<<<1024, 256>>>(buf3, 123904, sl + 2 * 128, bng + 128,
                                      bnb + 128, 1.f / 123904.f, bh3, bl3);
        conv_mma3_kernel<11, 11, 5, 5, 2><<<200, 256, MMA_SMEM>>>(
            bh3, bl3, wf4, buf4, sl + 3 * 128);
        relation_kernel<<<1024, 256, REL_SMEM>>>(
            buf4, lat, Wg1, bg1, Wg2, bg2, Wg3, bg3,
            sl + 3 * 128, bng + 192, bnb + 192, 1.f / 25600.f, im, gp);
    }
    final_head_kernel<<<128, 256>>>(lat, Wf1, bf1, Wf2, bf2, Wf3, bf3, out);
}

// round 12
// speedup vs baseline: 1.0529x; 1.0529x over previous
#include <cuda_runtime.h>
#include <cuda_bf16.h>
#include <math.h>
#include <stdint.h>

// ---------------------------------------------------------------------------
// RelationNetworks forward. B=1024, C=64, L=64, H=64, IMG=27.
// conv chain: 27 ->(s1) 25 ->(s1) 23 ->(s2) 11 ->(s2) 5
// Activations NHWC. conv2/3/4 via mma.sync m16n8k16 bf16, 2-term hi/lo split,
// 3-pass product, fp32 accum. A fragments loaded with ldmatrix.x4 from
// row-major smem (stride 20 words, conflict-free). BN stats fused.
// ---------------------------------------------------------------------------

__device__ float d_buf1[1024 * 625 * 64];
__device__ float d_buf2[1024 * 529 * 64];
__device__ float d_buf3[1024 * 121 * 64];
__device__ float d_buf4[1024 * 25 * 64];
__device__ float d_Wt1[32 * 64];          // conv1 [k pad32][oc]
// fragment-major packed bf16 weights:
// idx = (ch*2+wn)*256 + nf*64 + step*32 + lane -> {b0h, b1h, b0l, b1l}
__device__ uint4 d_Wf2[9216];
__device__ uint4 d_Wf3[9216];
__device__ uint4 d_Wf4[9216];
__device__ float d_statsA[8 * 128];
__device__ float d_Ssum[2];
__device__ float d_g0[1024 * 64];
__device__ float d_g1[1024 * 64];

// ---------------------------- helpers --------------------------------------
__device__ __forceinline__ uint16_t f2bf(float x, float& lo) {
    __nv_bfloat16 h = __float2bfloat16_rn(x);
    lo = x - __bfloat162float(h);
    return *(uint16_t*)&h;
}

__device__ __forceinline__ void mma_bf16(float c[4], const uint32_t a[4],
                                         uint32_t b0, uint32_t b1) {
    asm volatile(
        "mma.sync.aligned.m16n8k16.row.col.f32.bf16.bf16.f32 "
        "{%0,%1,%2,%3}, {%4,%5,%6,%7}, {%8,%9}, {%0,%1,%2,%3};"
        : "+f"(c[0]), "+f"(c[1]), "+f"(c[2]), "+f"(c[3])
        : "r"(a[0]), "r"(a[1]), "r"(a[2]), "r"(a[3]), "r"(b0), "r"(b1));
}

__device__ __forceinline__ void ldsm_x4(uint32_t r[4], uint32_t addr) {
    asm volatile(
        "ldmatrix.sync.aligned.m8n8.x4.shared.b16 {%0,%1,%2,%3}, [%4];"
        : "=r"(r[0]), "=r"(r[1]), "=r"(r[2]), "=r"(r[3]) : "r"(addr));
}

// ---------------------------- small kernels --------------------------------
__global__ void zero_misc_kernel() {
    int t = threadIdx.x;
    if (t < 1024) d_statsA[t] = 0.f;
    if (t < 2) d_Ssum[t] = 0.f;
}

__global__ void prep_weights_kernel(const float* __restrict__ Wc1,
                                    const float* __restrict__ Wc2,
                                    const float* __restrict__ Wc3,
                                    const float* __restrict__ Wc4) {
    int i = blockIdx.x * blockDim.x + threadIdx.x;
    if (i < 32 * 64) {
        int k = i >> 6, oc = i & 63;
        d_Wt1[i] = (k < 27) ? Wc1[oc * 27 + (k % 3) * 9 + (k / 3)] : 0.f;
    }
    if (i < 9216) {
        int lane = i & 31;
        int step = (i >> 5) & 1;
        int nf = (i >> 6) & 3;
        int wn = (i >> 8) & 1;
        int ch = i >> 9;                       // 0..17
        int n = wn * 32 + nf * 8 + (lane >> 2);
        int lt = lane & 3;
        int kb = ch * 32 + step * 16;
        int ks[4] = {kb + 2 * lt, kb + 2 * lt + 1, kb + 2 * lt + 8, kb + 2 * lt + 9};
        const float* Ws[3] = {Wc2, Wc3, Wc4};
        uint4* Wd[3] = {d_Wf2, d_Wf3, d_Wf4};
#pragma unroll
        for (int L = 0; L < 3; L++) {
            uint16_t h[4];
            float lo[4];
#pragma unroll
            for (int e = 0; e < 4; e++) {
                int k = ks[e];
                float v = Ws[L][n * 576 + (k & 63) * 9 + (k >> 6)];
                h[e] = f2bf(v, lo[e]);
            }
            uint16_t l0 = f2bf(lo[0], lo[0]), l1 = f2bf(lo[1], lo[1]);
            uint16_t l2 = f2bf(lo[2], lo[2]), l3 = f2bf(lo[3], lo[3]);
            Wd[L][i] = make_uint4(((uint32_t)h[1] << 16) | h[0],
                                  ((uint32_t)h[3] << 16) | h[2],
                                  ((uint32_t)l1 << 16) | l0,
                                  ((uint32_t)l3 << 16) | l2);
        }
    }
}

__global__ void att_sum_kernel(const float* __restrict__ lat) {
    int i = blockIdx.x * blockDim.x + threadIdx.x;
    float p0 = 0.f, p1 = 0.f;
    for (int idx = i; idx < 65536; idx += gridDim.x * blockDim.x) {
        int b = idx >> 6, c = idx & 63;
        p0 += expf(lat[(b * 4 + 2) * 64 + c]);
        p1 += expf(lat[(b * 4 + 3) * 64 + c]);
    }
#pragma unroll
    for (int o = 16; o; o >>= 1) {
        p0 += __shfl_down_sync(0xffffffffu, p0, o);
        p1 += __shfl_down_sync(0xffffffffu, p1, o);
    }
    if ((threadIdx.x & 31) == 0) {
        atomicAdd(&d_Ssum[0], p0);
        atomicAdd(&d_Ssum[1], p1);
    }
}

// ---- conv1: NCHW input (3 ch), NHWC raw output + shuffle-reduced stats ----
__global__ void __launch_bounds__(256) conv1_kernel(
    const float* __restrict__ in, const float* __restrict__ Wt,
    float* __restrict__ out, float* __restrict__ slot) {
    constexpr int BK = 16;
    __shared__ float As[BK][64];
    __shared__ float Bs[BK][64];
    __shared__ float sred[2][64][8];

    const int tid = threadIdx.x;
    const int lane = tid & 31, warp = tid >> 5;
    const int tx = tid & 15, ty = tid >> 4;
    const int m0 = blockIdx.x * 64;

    const int mi = tid >> 2;
    const int kb = (tid & 3) * 4;
    const int mg = m0 + mi;
    const int bI = mg / 625;
    const int sp = mg - bI * 625;
    const int oy = sp / 25;
    const int ox = sp - oy * 25;
    const float* inb = in + ((size_t)bI * 3) * 729 + oy * 27 + ox;

    float acc[4][4];
#pragma unroll
    for (int i = 0; i < 4; i++)
#pragma unroll
        for (int j = 0; j < 4; j++) acc[i][j] = 0.f;

    for (int k0 = 0; k0 < 32; k0 += BK) {
        {
            int ki = tid >> 4;
            int oc = (tid & 15) * 4;
            *(float4*)&Bs[ki][oc] = *(const float4*)(Wt + (k0 + ki) * 64 + oc);
        }
#pragma unroll
        for (int j = 0; j < 4; j++) {
            int k = k0 + kb + j;
            float v = 0.f;
            if (k < 27) {
                int w = k / 3, ic = k - w * 3;
                int ky = w / 3, kx = w - ky * 3;
                v = inb[ic * 729 + ky * 27 + kx];
            }
            As[kb + j][mi] = v;
        }
        __syncthreads();
#pragma unroll
        for (int kk = 0; kk < BK; kk++) {
            float4 a4 = *(float4*)&As[kk][ty * 4];
            float4 b4 = *(float4*)&Bs[kk][tx * 4];
            float av[4] = {a4.x, a4.y, a4.z, a4.w};
            float bw[4] = {b4.x, b4.y, b4.z, b4.w};
#pragma unroll
            for (int i = 0; i < 4; i++)
#pragma unroll
                for (int j = 0; j < 4; j++)
                    acc[i][j] = fmaf(av[i], bw[j], acc[i][j]);
        }
        __syncthreads();
    }
#pragma unroll
    for (int j = 0; j < 4; j++) {
        float s = 0.f, q = 0.f;
#pragma unroll
        for (int i = 0; i < 4; i++) {
            float v = acc[i][j];
            s += v;
            q += v * v;
        }
        s += __shfl_down_sync(0xffffffffu, s, 16);
        q += __shfl_down_sync(0xffffffffu, q, 16);
        if (lane < 16) {
            sred[0][lane * 4 + j][warp] = s;
            sred[1][lane * 4 + j][warp] = q;
        }
    }
#pragma unroll
    for (int i = 0; i < 4; i++) {
        float4 v = make_float4(acc[i][0], acc[i][1], acc[i][2], acc[i][3]);
        *(float4*)(out + (size_t)(m0 + ty * 4 + i) * 64 + tx * 4) = v;
    }
    __syncthreads();
    if (tid < 128) {
        int s = tid >> 6, c = tid & 63;
        float v = 0.f;
#pragma unroll
        for (int w = 0; w < 8; w++) v += sred[s][c][w];
        atomicAdd(&slot[s * 64 + c], v);
    }
}

// ---- conv64 via mma.sync bf16 hi/lo (3-pass), ldmatrix A fragments --------
// A smem row-major [row][16 k2 words, stride 20] per buffer; hi then lo.
template <int IH, int IW, int OH, int OW, int STRIDE>
__global__ void __launch_bounds__(256) conv_mma3_kernel(
    const float* __restrict__ in, const uint4* __restrict__ Wf,
    float* __restrict__ out,
    const float* __restrict__ stats, const float* __restrict__ bn_g,
    const float* __restrict__ bn_b, float invN, float* __restrict__ slot) {
    constexpr int OSP = OH * OW;
    constexpr int STG_BYTES = 20480;   // per stage: hi 10240 + lo 10240
    extern __shared__ uint32_t smu[];
    __shared__ float sBn[128];
    __shared__ float sred[2][64][8];

    uint32_t smem_base;
    asm("{ .reg .u64 t; cvta.to.shared.u64 t, %1; cvt.u32.u64 %0, t; }"
        : "=r"(smem_base) : "l"(smu));

    const int tid = threadIdx.x;
    const int lane = tid & 31, warp = tid >> 5;
    const int wm = warp & 3, wn = warp >> 2;
    const int lg = lane >> 2, lt = lane & 3;

    if (tid < 64) {
        float s = stats[tid], q = stats[64 + tid];
        float mean = s * invN;
        float var = q * invN - mean * mean;
        float sc = bn_g[tid] * rsqrtf(var + 1e-5f);
        sBn[tid] = sc;
        sBn[64 + tid] = bn_b[tid] - mean * sc;
    }

    // producer coords: one row per 2 threads, 16 k each
    const int row = tid >> 1;
    const int khalf = tid & 1;
    const int mg = blockIdx.x * 128 + row;
    const int bI = mg / OSP;
    const int sp = mg - bI * OSP;
    const int oy = sp / OW;
    const int ox = sp - oy * OW;
    const float* inb = in + (((size_t)bI * IH + oy * STRIDE) * IW + ox * STRIDE) * 64;

    float c[2][4][4];
#pragma unroll
    for (int m = 0; m < 2; m++)
#pragma unroll
        for (int n = 0; n < 4; n++)
#pragma unroll
            for (int e = 0; e < 4; e++) c[m][n][e] = 0.f;

    __syncthreads();

    // fill chunk ch into stage s: BN+ReLU+split, row-major packed store
    auto fill = [&](int s, int ch) {
        const int w = ch >> 1;
        const int ic0 = (ch & 1) * 32;
        const int ky = w / 3, kx = w - ky * 3;
        const float* src = inb + (ky * IW + kx) * 64 + ic0 + khalf * 16;
        uint32_t oh[8], ol[8];
#pragma unroll
        for (int j = 0; j < 4; j++) {
            float4 v = *(const float4*)(src + j * 4);
            int icb = ic0 + khalf * 16 + j * 4;
            float4 sc = *(const float4*)&sBn[icb];
            float4 sh = *(const float4*)&sBn[64 + icb];
            float x0 = fmaxf(fmaf(v.x, sc.x, sh.x), 0.f);
            float x1 = fmaxf(fmaf(v.y, sc.y, sh.y), 0.f);
            float x2 = fmaxf(fmaf(v.z, sc.z, sh.z), 0.f);
            float x3 = fmaxf(fmaf(v.w, sc.w, sh.w), 0.f);
            float r0, r1, r2, r3;
            uint16_t h0 = f2bf(x0, r0), h1 = f2bf(x1, r1);
            uint16_t h2 = f2bf(x2, r2), h3 = f2bf(x3, r3);
            uint16_t l0 = f2bf(r0, r0), l1 = f2bf(r1, r1);
            uint16_t l2 = f2bf(r2, r2), l3 = f2bf(r3, r3);
            oh[j * 2] = ((uint32_t)h1 << 16) | h0;
            oh[j * 2 + 1] = ((uint32_t)h3 << 16) | h2;
            ol[j * 2] = ((uint32_t)l1 << 16) | l0;
            ol[j * 2 + 1] = ((uint32_t)l3 << 16) | l2;
        }
        uint32_t aH = smem_base + s * STG_BYTES + row * 80 + khalf * 32;
        uint32_t aL = aH + 10240;
        asm volatile("st.shared.v4.b32 [%0], {%1,%2,%3,%4};"
                     :: "r"(aH), "r"(oh[0]), "r"(oh[1]), "r"(oh[2]), "r"(oh[3]) : "memory");
        asm volatile("st.shared.v4.b32 [%0], {%1,%2,%3,%4};"
                     :: "r"(aH + 16), "r"(oh[4]), "r"(oh[5]), "r"(oh[6]), "r"(oh[7]) : "memory");
        asm volatile("st.shared.v4.b32 [%0], {%1,%2,%3,%4};"
                     :: "r"(aL), "r"(ol[0]), "r"(ol[1]), "r"(ol[2]), "r"(ol[3]) : "memory");
        asm volatile("st.shared.v4.b32 [%0], {%1,%2,%3,%4};"
                     :: "r"(aL + 16), "r"(ol[4]), "r"(ol[5]), "r"(ol[6]), "r"(ol[7]) : "memory");
    };

    fill(0, 0);
    __syncthreads();

#pragma unroll 1
    for (int ch = 0; ch < 18; ch++) {
        if (ch + 1 < 18) fill((ch + 1) & 1, ch + 1);

        const uint32_t aHb = smem_base + (ch & 1) * STG_BYTES;
        const uint4* wp = Wf + (size_t)(ch * 2 + wn) * 256 + lane;
#pragma unroll
        for (int step = 0; step < 2; step++) {
            uint32_t ah[2][4], al[2][4];
#pragma unroll
            for (int m = 0; m < 2; m++) {
                uint32_t addr = aHb + (wm * 32 + m * 16 + (lane & 15)) * 80 +
                                step * 32 + (lane >> 4) * 16;
                ldsm_x4(ah[m], addr);
                ldsm_x4(al[m], addr + 10240);
            }
#pragma unroll
            for (int nf = 0; nf < 4; nf++) {
                uint4 b = wp[nf * 64 + step * 32];
#pragma unroll
                for (int m = 0; m < 2; m++) {
                    mma_bf16(c[m][nf], ah[m], b.x, b.y);   // hi*hi
                    mma_bf16(c[m][nf], ah[m], b.z, b.w);   // hi*lo
                    mma_bf16(c[m][nf], al[m], b.x, b.y);   // lo*hi
                }
            }
        }
        __syncthreads();
    }

    // fused stats: per-col partials, stride-4 shuffle reduce, smem, atomics
#pragma unroll
    for (int nf = 0; nf < 4; nf++) {
#pragma unroll
        for (int e = 0; e < 2; e++) {
            float s = c[0][nf][e] + c[0][nf][e + 2] + c[1][nf][e] + c[1][nf][e + 2];
            float q = c[0][nf][e] * c[0][nf][e] + c[0][nf][e + 2] * c[0][nf][e + 2] +
                      c[1][nf][e] * c[1][nf][e] + c[1][nf][e + 2] * c[1][nf][e + 2];
#pragma unroll
            for (int o = 16; o >= 4; o >>= 1) {
                s += __shfl_down_sync(0xffffffffu, s, o);
                q += __shfl_down_sync(0xffffffffu, q, o);
            }
            if (lane < 4) {
                int col = wn * 32 + nf * 8 + lane * 2 + e;
                sred[0][col][warp] = s;
                sred[1][col][warp] = q;
            }
        }
    }

    // output stores
#pragma unroll
    for (int m = 0; m < 2; m++) {
        int r = blockIdx.x * 128 + wm * 32 + m * 16 + lg;
#pragma unroll
        for (int nf = 0; nf < 4; nf++) {
            int col = wn * 32 + nf * 8 + lt * 2;
            *(float2*)(out + (size_t)r * 64 + col) =
                make_float2(c[m][nf][0], c[m][nf][1]);
            *(float2*)(out + (size_t)(r + 8) * 64 + col) =
                make_float2(c[m][nf][2], c[m][nf][3]);
        }
    }
    __syncthreads();
    if (tid < 128) {
        int si = tid >> 6, col = tid & 63;
        int wbase = (col < 32) ? 0 : 4;
        float v = sred[si][col][wbase] + sred[si][col][wbase + 1] +
                  sred[si][col][wbase + 2] + sred[si][col][wbase + 3];
        atomicAdd(&slot[si * 64 + col], v);
    }
}

// ---- relation network: one block per batch element ------------------------
__global__ void __launch_bounds__(256) relation_kernel(
    const float* __restrict__ conv4, const float* __restrict__ lat,
    const float* __restrict__ Wg1, const float* __restrict__ bg1,
    const float* __restrict__ Wg2, const float* __restrict__ bg2,
    const float* __restrict__ Wg3, const float* __restrict__ bg3,
    const float* __restrict__ stats, const float* __restrict__ bn_g,
    const float* __restrict__ bn_b, float invN,
    int im, float* __restrict__ gout) {
    extern __shared__ float sm[];
    float* sW2 = sm;
    float* sW3 = sm + 4096;
    float* sTi = sm + 8192;
    float* sTj = sm + 9792;
    float* sCT = sm + 11392;
    float* sTw = sm + 13042;
    float* sH  = sm + 13108;
    float* sGp = sm + 15156;
    __shared__ float sBn[128];

    const int tid = threadIdx.x;
    const int b = blockIdx.x;
    const int lane = tid & 31, warp = tid >> 5;

    if (tid < 64) {
        float s = stats[tid], q = stats[64 + tid];
        float mean = s * invN;
        float var = q * invN - mean * mean;
        float sc = bn_g[tid] * rsqrtf(var + 1e-5f);
        sBn[tid] = sc;
        sBn[64 + tid] = bn_b[tid] - mean * sc;
    }
    for (int i = tid; i < 4096; i += 256) {
        sW2[i] = Wg2[i];
        sW3[i] = Wg3[i];
    }
    __syncthreads();

    const float invS = 1.f / (d_Ssum[im] + 1e-9f);
    const float* aRow = lat + ((size_t)b * 4 + 2 + im) * 64;
    const float* wRow = lat + ((size_t)b * 4 + im) * 64;

    for (int i = tid; i < 1600; i += 256) {
        int p = i >> 6, cc = i & 63;
        float v = conv4[((size_t)b * 25 + p) * 64 + cc];
        v = fmaxf(fmaf(v, sBn[cc], sBn[64 + cc]), 0.f);
        v *= expf(aRow[cc]) * invS;
        sCT[p * 66 + cc] = v;
    }
    if (tid < 50) {
        int p = tid % 25, cc = tid / 25;
        sCT[p * 66 + 64 + cc] = (cc == 0) ? (float)(p % 5) - 2.f : (float)(p / 5) - 2.f;
    }
    if (tid < 64) {
        float acc = bg1[tid];
        for (int cc = 0; cc < 64; cc++)
            acc = fmaf(wRow[cc], Wg1[(132 + cc) * 64 + tid], acc);
        sTw[tid] = acc;
    }
    __syncthreads();

    for (int o = tid; o < 1600; o += 256) {
        int p = o >> 6, h = o & 63;
        float aj = 0.f, ai = 0.f;
        for (int cc = 0; cc < 66; cc++) {
            float ctv = sCT[p * 66 + cc];
            aj = fmaf(ctv, Wg1[cc * 64 + h], aj);
            ai = fmaf(ctv, Wg1[(66 + cc) * 64 + h], ai);
        }
        sTj[p * 64 + h] = aj;
        sTi[p * 64 + h] = ai;
    }
    __syncthreads();

    const float twA = sTw[lane], twB = sTw[lane + 32];
    const float b2A = bg2[lane], b2B = bg2[lane + 32];
    const float b3A = bg3[lane], b3B = bg3[lane + 32];
    float gA = 0.f, gB = 0.f;
    float* hw = sH + warp * 256;

    for (int it = 0; it < 20; it++) {
        const int base = it * 32 + warp * 4;
#pragma unroll
        for (int s = 0; s < 4; s++) {
            int pr = base + s;
            bool vld = pr < 625;
            int p = vld ? pr / 25 : 0, qq = vld ? pr % 25 : 0;
            hw[lane * 4 + s] = fmaxf(sTi[p * 64 + lane] + sTj[qq * 64 + lane] + twA, 0.f);
            hw[(lane + 32) * 4 + s] =
                fmaxf(sTi[p * 64 + lane + 32] + sTj[qq * 64 + lane + 32] + twB, 0.f);
        }
        __syncwarp();

        float a0[4], a1[4];
#pragma unroll
        for (int s = 0; s < 4; s++) { a0[s] = b2A; a1[s] = b2B; }
#pragma unroll 8
        for (int k = 0; k < 64; k++) {
            float w0 = sW2[k * 64 + lane], w1 = sW2[k * 64 + lane + 32];
            float4 hv = *(float4*)&hw[k * 4];
            a0[0] = fmaf(hv.x, w0, a0[0]); a1[0] = fmaf(hv.x, w1, a1[0]);
            a0[1] = fmaf(hv.y, w0, a0[1]); a1[1] = fmaf(hv.y, w1, a1[1]);
            a0[2] = fmaf(hv.z, w0, a0[2]); a1[2] = fmaf(hv.z, w1, a1[2]);
            a0[3] = fmaf(hv.w, w0, a0[3]); a1[3] = fmaf(hv.w, w1, a1[3]);
        }
        __syncwarp();
#pragma unroll
        for (int s = 0; s < 4; s++) {
            hw[lane * 4 + s] = fmaxf(a0[s], 0.f);
            hw[(lane + 32) * 4 + s] = fmaxf(a1[s], 0.f);
        }
        __syncwarp();

#pragma unroll
        for (int s = 0; s < 4; s++) { a0[s] = b3A; a1[s] = b3B; }
#pragma unroll 8
        for (int k = 0; k < 64; k++) {
            float w0 = sW3[k * 64 + lane], w1 = sW3[k * 64 + lane + 32];
            float4 hv = *(float4*)&hw[k * 4];
            a0[0] = fmaf(hv.x, w0, a0[0]); a1[0] = fmaf(hv.x, w1, a1[0]);
            a0[1] = fmaf(hv.y, w0, a0[1]); a1[1] = fmaf(hv.y, w1, a1[1]);
            a0[2] = fmaf(hv.z, w0, a0[2]); a1[2] = fmaf(hv.z, w1, a1[2]);
            a0[3] = fmaf(hv.w, w0, a0[3]); a1[3] = fmaf(hv.w, w1, a1[3]);
        }
#pragma unroll
        for (int s = 0; s < 4; s++) {
            if (base + s < 625) {
                gA += fmaxf(a0[s], 0.f);
                gB += fmaxf(a1[s], 0.f);
            }
        }
        __syncwarp();
    }
    sGp[warp * 64 + lane] = gA;
    sGp[warp * 64 + lane + 32] = gB;
    __syncthreads();
    if (tid < 64) {
        float s = 0.f;
#pragma unroll
        for (int w = 0; w < 8; w++) s += sGp[w * 64 + tid];
        gout[(size_t)b * 64 + tid] = s;
    }
}

__global__ void final_head_kernel(const float* __restrict__ lat,
                                  const float* __restrict__ Wf1, const float* __restrict__ bf1,
                                  const float* __restrict__ Wf2, const float* __restrict__ bf2,
                                  const float* __restrict__ Wf3, const float* __restrict__ bf3,
                                  float* __restrict__ out) {
    __shared__ float sh1[8][64];
    int tid = threadIdx.x, lane = tid & 31, warp = tid >> 5;
    int b = blockIdx.x * 8 + warp;
    float a0 = bf1[lane], a1 = bf1[lane + 32];
    const float* g0 = d_g0 + (size_t)b * 64;
    const float* g1 = d_g1 + (size_t)b * 64;
    const float* lr = lat + (size_t)b * 256;
    for (int k = 0; k < 64; k++) {
        float g = g0[k];
        a0 = fmaf(g, Wf1[k * 64 + lane], a0);
        a1 = fmaf(g, Wf1[k * 64 + lane + 32], a1);
    }
    for (int k = 0; k < 64; k++) {
        float g = g1[k];
        a0 = fmaf(g, Wf1[(64 + k) * 64 + lane], a0);
        a1 = fmaf(g, Wf1[(64 + k) * 64 + lane + 32], a1);
    }
    for (int k = 0; k < 256; k++) {
        float g = lr[k];
        a0 = fmaf(g, Wf1[(128 + k) * 64 + lane], a0);
        a1 = fmaf(g, Wf1[(128 + k) * 64 + lane + 32], a1);
    }
    sh1[warp][lane] = fmaxf(a0, 0.f);
    sh1[warp][lane + 32] = fmaxf(a1, 0.f);
    __syncwarp();
    float c = bf2[lane];
    for (int k = 0; k < 64; k++) c = fmaf(sh1[warp][k], Wf2[k * 32 + lane], c);
    c = fmaxf(c, 0.f);
    float v = c * Wf3[lane];
#pragma unroll
    for (int o = 16; o; o >>= 1) v += __shfl_down_sync(0xffffffffu, v, o);
    if (lane == 0) out[b] = v + bf3[0];
}

extern "C" void kernel_launch(void* const* d_in, const int* in_sizes, int n_in,
                              void* d_out, int out_size) {
    const float* x0 = (const float*)d_in[0];
    const float* x1 = (const float*)d_in[1];
    const float* lat = (const float*)d_in[2];
    const float* Wc1 = (const float*)d_in[3];
    const float* Wc2 = (const float*)d_in[4];
    const float* Wc3 = (const float*)d_in[5];
    const float* Wc4 = (const float*)d_in[6];
    const float* bng = (const float*)d_in[7];
    const float* bnb = (const float*)d_in[8];
    const float* Wg1 = (const float*)d_in[9];
    const float* bg1 = (const float*)d_in[10];
    const float* Wg2 = (const float*)d_in[11];
    const float* bg2 = (const float*)d_in[12];
    const float* Wg3 = (const float*)d_in[13];
    const float* bg3 = (const float*)d_in[14];
    const float* Wf1 = (const float*)d_in[15];
    const float* bf1 = (const float*)d_in[16];
    const float* Wf2 = (const float*)d_in[17];
    const float* bf2 = (const float*)d_in[18];
    const float* Wf3 = (const float*)d_in[19];
    const float* bf3 = (const float*)d_in[20];
    float* out = (float*)d_out;

    float *buf1, *buf2, *buf3, *buf4, *wt1, *statsA, *g0p, *g1p;
    uint4 *wf2, *wf3, *wf4;
    cudaGetSymbolAddress((void**)&buf1, d_buf1);
    cudaGetSymbolAddress((void**)&buf2, d_buf2);
    cudaGetSymbolAddress((void**)&buf3, d_buf3);
    cudaGetSymbolAddress((void**)&buf4, d_buf4);
    cudaGetSymbolAddress((void**)&wt1, d_Wt1);
    cudaGetSymbolAddress((void**)&wf2, d_Wf2);
    cudaGetSymbolAddress((void**)&wf3, d_Wf3);
    cudaGetSymbolAddress((void**)&wf4, d_Wf4);
    cudaGetSymbolAddress((void**)&statsA, d_statsA);
    cudaGetSymbolAddress((void**)&g0p, d_g0);
    cudaGetSymbolAddress((void**)&g1p, d_g1);

    const int REL_SMEM = 15668 * 4;
    cudaFuncSetAttribute(relation_kernel, cudaFuncAttributeMaxDynamicSharedMemorySize, REL_SMEM);
    const int MMA_SMEM = 2 * 20480;   // 40960 B
    cudaFuncSetAttribute(conv_mma3_kernel<25, 25, 23, 23, 1>,
                         cudaFuncAttributeMaxDynamicSharedMemorySize, MMA_SMEM);
    cudaFuncSetAttribute(conv_mma3_kernel<23, 23, 11, 11, 2>,
                         cudaFuncAttributeMaxDynamicSharedMemorySize, MMA_SMEM);
    cudaFuncSetAttribute(conv_mma3_kernel<11, 11, 5, 5, 2>,
                         cudaFuncAttributeMaxDynamicSharedMemorySize, MMA_SMEM);

    zero_misc_kernel<<<1, 1024>>>();
    prep_weights_kernel<<<36, 256>>>(Wc1, Wc2, Wc3, Wc4);
    att_sum_kernel<<<64, 512>>>(lat);

    for (int im = 0; im < 2; im++) {
        const float* x = im ? x1 : x0;
        float* gp = im ? g1p : g0p;
        float* sl = statsA + im * 4 * 128;

        conv1_kernel<<<10000, 256>>>(x, wt1, buf1, sl + 0 * 128);
        conv_mma3_kernel<25, 25, 23, 23, 1><<<4232, 256, MMA_SMEM>>>(
            buf1, wf2, buf2, sl + 0 * 128, bng + 0, bnb + 0, 1.f / 640000.f,
            sl + 1 * 128);
        conv_mma3_kernel<23, 23, 11, 11, 2><<<968, 256, MMA_SMEM>>>(
            buf2, wf3, buf3, sl + 1 * 128, bng + 64, bnb + 64, 1.f / 541696.f,
            sl + 2 * 128);
        conv_mma3_kernel<11, 11, 5, 5, 2><<<200, 256, MMA_SMEM>>>(
            buf3, wf4, buf4, sl + 2 * 128, bng + 128, bnb + 128, 1.f / 123904.f,
            sl + 3 * 128);
        relation_kernel<<<1024, 256, REL_SMEM>>>(
            buf4, lat, Wg1, bg1, Wg2, bg2, Wg3, bg3,
            sl + 3 * 128, bng + 192, bnb + 192, 1.f / 25600.f, im, gp);
    }
    final_head_kernel<<<128, 256>>>(lat, Wf1, bf1, Wf2, bf2, Wf3, bf3, out);
}

// round 13
// speedup vs baseline: 1.1169x; 1.0608x over previous
#include <cuda_runtime.h>
#include <cuda_bf16.h>
#include <math.h>
#include <stdint.h>

// ---------------------------------------------------------------------------
// RelationNetworks forward. B=1024, C=64, L=64, H=64, IMG=27.
// conv chain: 27 ->(s1) 25 ->(s1) 23 ->(s2) 11 ->(s2) 5
// Activations NHWC. conv2/3/4 via mma.sync m16n8k16 bf16, 2-term hi/lo split,
// 3-pass product (pass-outermost for mma ILP), fp32 accum. BN stats fused.
// ---------------------------------------------------------------------------

__device__ float d_buf1[1024 * 625 * 64];
__device__ float d_buf2[1024 * 529 * 64];
__device__ float d_buf3[1024 * 121 * 64];
__device__ float d_buf4[1024 * 25 * 64];
__device__ float d_Wt1[32 * 64];          // conv1 [k pad32][oc]
// fragment-major packed bf16 weights:
// idx = (ch*2+wn)*256 + nf*64 + step*32 + lane -> {b0h, b1h, b0l, b1l}
__device__ uint4 d_Wf2[9216];
__device__ uint4 d_Wf3[9216];
__device__ uint4 d_Wf4[9216];
__device__ float d_statsA[8 * 128];
__device__ float d_Ssum[2];
__device__ float d_g0[1024 * 64];
__device__ float d_g1[1024 * 64];

// ---------------------------- helpers --------------------------------------
__device__ __forceinline__ uint16_t f2bf(float x, float& lo) {
    __nv_bfloat16 h = __float2bfloat16_rn(x);
    lo = x - __bfloat162float(h);
    return *(uint16_t*)&h;
}

__device__ __forceinline__ void mma_bf16(float c[4], const uint32_t a[4],
                                         uint32_t b0, uint32_t b1) {
    asm volatile(
        "mma.sync.aligned.m16n8k16.row.col.f32.bf16.bf16.f32 "
        "{%0,%1,%2,%3}, {%4,%5,%6,%7}, {%8,%9}, {%0,%1,%2,%3};"
        : "+f"(c[0]), "+f"(c[1]), "+f"(c[2]), "+f"(c[3])
        : "r"(a[0]), "r"(a[1]), "r"(a[2]), "r"(a[3]), "r"(b0), "r"(b1));
}

// ---------------------------- small kernels --------------------------------
__global__ void zero_misc_kernel() {
    int t = threadIdx.x;
    if (t < 1024) d_statsA[t] = 0.f;
    if (t < 2) d_Ssum[t] = 0.f;
}

__global__ void prep_weights_kernel(const float* __restrict__ Wc1,
                                    const float* __restrict__ Wc2,
                                    const float* __restrict__ Wc3,
                                    const float* __restrict__ Wc4) {
    int i = blockIdx.x * blockDim.x + threadIdx.x;
    if (i < 32 * 64) {
        int k = i >> 6, oc = i & 63;
        d_Wt1[i] = (k < 27) ? Wc1[oc * 27 + (k % 3) * 9 + (k / 3)] : 0.f;
    }
    if (i < 9216) {
        int lane = i & 31;
        int step = (i >> 5) & 1;
        int nf = (i >> 6) & 3;
        int wn = (i >> 8) & 1;
        int ch = i >> 9;                       // 0..17
        int n = wn * 32 + nf * 8 + (lane >> 2);
        int lt = lane & 3;
        int kb = ch * 32 + step * 16;
        int ks[4] = {kb + 2 * lt, kb + 2 * lt + 1, kb + 2 * lt + 8, kb + 2 * lt + 9};
        const float* Ws[3] = {Wc2, Wc3, Wc4};
        uint4* Wd[3] = {d_Wf2, d_Wf3, d_Wf4};
#pragma unroll
        for (int L = 0; L < 3; L++) {
            uint16_t h[4];
            float lo[4];
#pragma unroll
            for (int e = 0; e < 4; e++) {
                int k = ks[e];
                float v = Ws[L][n * 576 + (k & 63) * 9 + (k >> 6)];
                h[e] = f2bf(v, lo[e]);
            }
            uint16_t l0 = f2bf(lo[0], lo[0]), l1 = f2bf(lo[1], lo[1]);
            uint16_t l2 = f2bf(lo[2], lo[2]), l3 = f2bf(lo[3], lo[3]);
            Wd[L][i] = make_uint4(((uint32_t)h[1] << 16) | h[0],
                                  ((uint32_t)h[3] << 16) | h[2],
                                  ((uint32_t)l1 << 16) | l0,
                                  ((uint32_t)l3 << 16) | l2);
        }
    }
}

__global__ void att_sum_kernel(const float* __restrict__ lat) {
    int i = blockIdx.x * blockDim.x + threadIdx.x;
    float p0 = 0.f, p1 = 0.f;
    for (int idx = i; idx < 65536; idx += gridDim.x * blockDim.x) {
        int b = idx >> 6, c = idx & 63;
        p0 += expf(lat[(b * 4 + 2) * 64 + c]);
        p1 += expf(lat[(b * 4 + 3) * 64 + c]);
    }
#pragma unroll
    for (int o = 16; o; o >>= 1) {
        p0 += __shfl_down_sync(0xffffffffu, p0, o);
        p1 += __shfl_down_sync(0xffffffffu, p1, o);
    }
    if ((threadIdx.x & 31) == 0) {
        atomicAdd(&d_Ssum[0], p0);
        atomicAdd(&d_Ssum[1], p1);
    }
}

// ---- conv1: NCHW input (3 ch), NHWC raw output + fused stats --------------
__global__ void __launch_bounds__(256) conv1_kernel(
    const float* __restrict__ in, const float* __restrict__ Wt,
    float* __restrict__ out, float* __restrict__ slot) {
    constexpr int BK = 16;
    __shared__ float As[BK][64];
    __shared__ float Bs[BK][64];
    __shared__ float red[2][64][16];

    const int tid = threadIdx.x;
    const int tx = tid & 15, ty = tid >> 4;
    const int m0 = blockIdx.x * 64;

    const int mi = tid >> 2;
    const int kb = (tid & 3) * 4;
    const int mg = m0 + mi;
    const int bI = mg / 625;
    const int sp = mg - bI * 625;
    const int oy = sp / 25;
    const int ox = sp - oy * 25;
    const float* inb = in + ((size_t)bI * 3) * 729 + oy * 27 + ox;

    float acc[4][4];
#pragma unroll
    for (int i = 0; i < 4; i++)
#pragma unroll
        for (int j = 0; j < 4; j++) acc[i][j] = 0.f;

    for (int k0 = 0; k0 < 32; k0 += BK) {
        {
            int ki = tid >> 4;
            int oc = (tid & 15) * 4;
            *(float4*)&Bs[ki][oc] = *(const float4*)(Wt + (k0 + ki) * 64 + oc);
        }
#pragma unroll
        for (int j = 0; j < 4; j++) {
            int k = k0 + kb + j;
            float v = 0.f;
            if (k < 27) {
                int w = k / 3, ic = k - w * 3;
                int ky = w / 3, kx = w - ky * 3;
                v = inb[ic * 729 + ky * 27 + kx];
            }
            As[kb + j][mi] = v;
        }
        __syncthreads();
#pragma unroll
        for (int kk = 0; kk < BK; kk++) {
            float4 a4 = *(float4*)&As[kk][ty * 4];
            float4 b4 = *(float4*)&Bs[kk][tx * 4];
            float av[4] = {a4.x, a4.y, a4.z, a4.w};
            float bw[4] = {b4.x, b4.y, b4.z, b4.w};
#pragma unroll
            for (int i = 0; i < 4; i++)
#pragma unroll
                for (int j = 0; j < 4; j++)
                    acc[i][j] = fmaf(av[i], bw[j], acc[i][j]);
        }
        __syncthreads();
    }
#pragma unroll
    for (int j = 0; j < 4; j++) {
        float s = 0.f, q = 0.f;
#pragma unroll
        for (int i = 0; i < 4; i++) {
            float v = acc[i][j];
            s += v;
            q += v * v;
        }
        red[0][tx * 4 + j][ty] = s;
        red[1][tx * 4 + j][ty] = q;
    }
#pragma unroll
    for (int i = 0; i < 4; i++) {
        float4 v = make_float4(acc[i][0], acc[i][1], acc[i][2], acc[i][3]);
        *(float4*)(out + (size_t)(m0 + ty * 4 + i) * 64 + tx * 4) = v;
    }
    __syncthreads();
    if (tid < 128) {
        int s = tid >> 6, c = tid & 63;
        float v = 0.f;
#pragma unroll
        for (int t = 0; t < 16; t++) v += red[s][c][t];
        atomicAdd(&slot[s * 64 + c], v);
    }
}

// ---- conv64 via mma.sync bf16 hi/lo (3-pass): BM=128, BN=64, BK=32 --------
// A smem as bf16x2 [k2 16][row pad136] per stage (hi then lo). Fused stats.
// mma passes issued pass-outermost: same-accumulator reuse distance = 8 mma.
template <int IH, int IW, int OH, int OW, int STRIDE>
__global__ void __launch_bounds__(256) conv_mma3_kernel(
    const float* __restrict__ in, const uint4* __restrict__ Wf,
    float* __restrict__ out,
    const float* __restrict__ stats, const float* __restrict__ bn_g,
    const float* __restrict__ bn_b, float invN, float* __restrict__ slot) {
    constexpr int OSP = OH * OW;
    constexpr int STG = 4352;                 // u32 per stage (hi 2176 + lo 2176)
    extern __shared__ uint32_t smu[];
    __shared__ float sBn[128];
    __shared__ float sred[2][64][8];

    const int tid = threadIdx.x;
    const int lane = tid & 31, warp = tid >> 5;
    const int wm = warp & 3, wn = warp >> 2;
    const int lg = lane >> 2, lt = lane & 3;

    if (tid < 64) {
        float s = stats[tid], q = stats[64 + tid];
        float mean = s * invN;
        float var = q * invN - mean * mean;
        float sc = bn_g[tid] * rsqrtf(var + 1e-5f);
        sBn[tid] = sc;
        sBn[64 + tid] = bn_b[tid] - mean * sc;
    }

    // producer coords: one row per 2 threads, 16 k each
    const int row = tid >> 1;
    const int khalf = tid & 1;
    const int mg = blockIdx.x * 128 + row;
    const int bI = mg / OSP;
    const int sp = mg - bI * OSP;
    const int oy = sp / OW;
    const int ox = sp - oy * OW;
    const float* inb = in + (((size_t)bI * IH + oy * STRIDE) * IW + ox * STRIDE) * 64;

    float c[2][4][4];
#pragma unroll
    for (int m = 0; m < 2; m++)
#pragma unroll
        for (int n = 0; n < 4; n++)
#pragma unroll
            for (int e = 0; e < 4; e++) c[m][n][e] = 0.f;

    __syncthreads();

    // fill chunk ch into stage s: BN+ReLU, bf16 hi/lo split, pack k-pairs
    auto fill = [&](int s, int ch) {
        const int w = ch >> 1;
        const int ic0 = (ch & 1) * 32;
        const int ky = w / 3, kx = w - ky * 3;
        uint32_t* aH = smu + s * STG;
        uint32_t* aL = aH + 2176;
        const float* src = inb + (ky * IW + kx) * 64 + ic0 + khalf * 16;
        float xs[16];
#pragma unroll
        for (int j = 0; j < 4; j++) {
            float4 v = *(const float4*)(src + j * 4);
            int icb = ic0 + khalf * 16 + j * 4;
            float4 sc = *(const float4*)&sBn[icb];
            float4 sh = *(const float4*)&sBn[64 + icb];
            xs[j * 4 + 0] = fmaxf(fmaf(v.x, sc.x, sh.x), 0.f);
            xs[j * 4 + 1] = fmaxf(fmaf(v.y, sc.y, sh.y), 0.f);
            xs[j * 4 + 2] = fmaxf(fmaf(v.z, sc.z, sh.z), 0.f);
            xs[j * 4 + 3] = fmaxf(fmaf(v.w, sc.w, sh.w), 0.f);
        }
#pragma unroll
        for (int jj = 0; jj < 8; jj++) {
            float r0, r1;
            uint16_t h0 = f2bf(xs[2 * jj], r0);
            uint16_t h1 = f2bf(xs[2 * jj + 1], r1);
            uint16_t l0 = f2bf(r0, r0);
            uint16_t l1 = f2bf(r1, r1);
            int k2g = khalf * 8 + jj;
            aH[k2g * 136 + row] = ((uint32_t)h1 << 16) | h0;
            aL[k2g * 136 + row] = ((uint32_t)l1 << 16) | l0;
        }
    };

    fill(0, 0);
    __syncthreads();

#pragma unroll 1
    for (int ch = 0; ch < 18; ch++) {
        if (ch + 1 < 18) fill((ch + 1) & 1, ch + 1);

        const uint32_t* aH = smu + (ch & 1) * STG;
        const uint32_t* aL = aH + 2176;
        const uint4* wp = Wf + (size_t)(ch * 2 + wn) * 256 + lane;
#pragma unroll
        for (int step = 0; step < 2; step++) {
            uint32_t ah[2][4], al[2][4];
#pragma unroll
            for (int m = 0; m < 2; m++) {
                int rf = wm * 32 + m * 16 + lg;
                int k2 = step * 8 + lt;
                ah[m][0] = aH[k2 * 136 + rf];
                ah[m][1] = aH[k2 * 136 + rf + 8];
                ah[m][2] = aH[(k2 + 4) * 136 + rf];
                ah[m][3] = aH[(k2 + 4) * 136 + rf + 8];
                al[m][0] = aL[k2 * 136 + rf];
                al[m][1] = aL[k2 * 136 + rf + 8];
                al[m][2] = aL[(k2 + 4) * 136 + rf];
                al[m][3] = aL[(k2 + 4) * 136 + rf + 8];
            }
            uint4 b[4];
#pragma unroll
            for (int nf = 0; nf < 4; nf++) b[nf] = wp[nf * 64 + step * 32];
            // pass-outermost: accumulator reuse distance = 8 mma
#pragma unroll
            for (int nf = 0; nf < 4; nf++)
#pragma unroll
                for (int m = 0; m < 2; m++)
                    mma_bf16(c[m][nf], ah[m], b[nf].x, b[nf].y);   // hi*hi
#pragma unroll
            for (int nf = 0; nf < 4; nf++)
#pragma unroll
                for (int m = 0; m < 2; m++)
                    mma_bf16(c[m][nf], ah[m], b[nf].z, b[nf].w);   // hi*lo
#pragma unroll
            for (int nf = 0; nf < 4; nf++)
#pragma unroll
                for (int m = 0; m < 2; m++)
                    mma_bf16(c[m][nf], al[m], b[nf].x, b[nf].y);   // lo*hi
        }
        __syncthreads();
    }

    // fused stats: per-col partials, stride-4 shuffle reduce, smem, atomics
#pragma unroll
    for (int nf = 0; nf < 4; nf++) {
#pragma unroll
        for (int e = 0; e < 2; e++) {
            float s = c[0][nf][e] + c[0][nf][e + 2] + c[1][nf][e] + c[1][nf][e + 2];
            float q = c[0][nf][e] * c[0][nf][e] + c[0][nf][e + 2] * c[0][nf][e + 2] +
                      c[1][nf][e] * c[1][nf][e] + c[1][nf][e + 2] * c[1][nf][e + 2];
#pragma unroll
            for (int o = 16; o >= 4; o >>= 1) {
                s += __shfl_down_sync(0xffffffffu, s, o);
                q += __shfl_down_sync(0xffffffffu, q, o);
            }
            if (lane < 4) {
                int col = wn * 32 + nf * 8 + lane * 2 + e;
                sred[0][col][warp] = s;
                sred[1][col][warp] = q;
            }
        }
    }

    // output stores
#pragma unroll
    for (int m = 0; m < 2; m++) {
        int r = blockIdx.x * 128 + wm * 32 + m * 16 + lg;
#pragma unroll
        for (int nf = 0; nf < 4; nf++) {
            int col = wn * 32 + nf * 8 + lt * 2;
            *(float2*)(out + (size_t)r * 64 + col) =
                make_float2(c[m][nf][0], c[m][nf][1]);
            *(float2*)(out + (size_t)(r + 8) * 64 + col) =
                make_float2(c[m][nf][2], c[m][nf][3]);
        }
    }
    __syncthreads();
    if (tid < 128) {
        int si = tid >> 6, col = tid & 63;
        int wbase = (col < 32) ? 0 : 4;
        float v = sred[si][col][wbase] + sred[si][col][wbase + 1] +
                  sred[si][col][wbase + 2] + sred[si][col][wbase + 3];
        atomicAdd(&slot[si * 64 + col], v);
    }
}

// ---- relation network: one block per batch element ------------------------
__global__ void __launch_bounds__(256) relation_kernel(
    const float* __restrict__ conv4, const float* __restrict__ lat,
    const float* __restrict__ Wg1, const float* __restrict__ bg1,
    const float* __restrict__ Wg2, const float* __restrict__ bg2,
    const float* __restrict__ Wg3, const float* __restrict__ bg3,
    const float* __restrict__ stats, const float* __restrict__ bn_g,
    const float* __restrict__ bn_b, float invN,
    int im, float* __restrict__ gout) {
    extern __shared__ float sm[];
    float* sW2 = sm;
    float* sW3 = sm + 4096;
    float* sTi = sm + 8192;
    float* sTj = sm + 9792;
    float* sCT = sm + 11392;
    float* sTw = sm + 13042;
    float* sH  = sm + 13108;
    float* sGp = sm + 15156;
    __shared__ float sBn[128];

    const int tid = threadIdx.x;
    const int b = blockIdx.x;
    const int lane = tid & 31, warp = tid >> 5;

    if (tid < 64) {
        float s = stats[tid], q = stats[64 + tid];
        float mean = s * invN;
        float var = q * invN - mean * mean;
        float sc = bn_g[tid] * rsqrtf(var + 1e-5f);
        sBn[tid] = sc;
        sBn[64 + tid] = bn_b[tid] - mean * sc;
    }
    for (int i = tid; i < 4096; i += 256) {
        sW2[i] = Wg2[i];
        sW3[i] = Wg3[i];
    }
    __syncthreads();

    const float invS = 1.f / (d_Ssum[im] + 1e-9f);
    const float* aRow = lat + ((size_t)b * 4 + 2 + im) * 64;
    const float* wRow = lat + ((size_t)b * 4 + im) * 64;

    for (int i = tid; i < 1600; i += 256) {
        int p = i >> 6, cc = i & 63;
        float v = conv4[((size_t)b * 25 + p) * 64 + cc];
        v = fmaxf(fmaf(v, sBn[cc], sBn[64 + cc]), 0.f);
        v *= expf(aRow[cc]) * invS;
        sCT[p * 66 + cc] = v;
    }
    if (tid < 50) {
        int p = tid % 25, cc = tid / 25;
        sCT[p * 66 + 64 + cc] = (cc == 0) ? (float)(p % 5) - 2.f : (float)(p / 5) - 2.f;
    }
    if (tid < 64) {
        float acc = bg1[tid];
        for (int cc = 0; cc < 64; cc++)
            acc = fmaf(wRow[cc], Wg1[(132 + cc) * 64 + tid], acc);
        sTw[tid] = acc;
    }
    __syncthreads();

    for (int o = tid; o < 1600; o += 256) {
        int p = o >> 6, h = o & 63;
        float aj = 0.f, ai = 0.f;
        for (int cc = 0; cc < 66; cc++) {
            float ctv = sCT[p * 66 + cc];
            aj = fmaf(ctv, Wg1[cc * 64 + h], aj);
            ai = fmaf(ctv, Wg1[(66 + cc) * 64 + h], ai);
        }
        sTj[p * 64 + h] = aj;
        sTi[p * 64 + h] = ai;
    }
    __syncthreads();

    const float twA = sTw[lane], twB = sTw[lane + 32];
    const float b2A = bg2[lane], b2B = bg2[lane + 32];
    const float b3A = bg3[lane], b3B = bg3[lane + 32];
    float gA = 0.f, gB = 0.f;
    float* hw = sH + warp * 256;

    for (int it = 0; it < 20; it++) {
        const int base = it * 32 + warp * 4;
#pragma unroll
        for (int s = 0; s < 4; s++) {
            int pr = base + s;
            bool vld = pr < 625;
            int p = vld ? pr / 25 : 0, qq = vld ? pr % 25 : 0;
            hw[lane * 4 + s] = fmaxf(sTi[p * 64 + lane] + sTj[qq * 64 + lane] + twA, 0.f);
            hw[(lane + 32) * 4 + s] =
                fmaxf(sTi[p * 64 + lane + 32] + sTj[qq * 64 + lane + 32] + twB, 0.f);
        }
        __syncwarp();

        float a0[4], a1[4];
#pragma unroll
        for (int s = 0; s < 4; s++) { a0[s] = b2A; a1[s] = b2B; }
#pragma unroll 8
        for (int k = 0; k < 64; k++) {
            float w0 = sW2[k * 64 + lane], w1 = sW2[k * 64 + lane + 32];
            float4 hv = *(float4*)&hw[k * 4];
            a0[0] = fmaf(hv.x, w0, a0[0]); a1[0] = fmaf(hv.x, w1, a1[0]);
            a0[1] = fmaf(hv.y, w0, a0[1]); a1[1] = fmaf(hv.y, w1, a1[1]);
            a0[2] = fmaf(hv.z, w0, a0[2]); a1[2] = fmaf(hv.z, w1, a1[2]);
            a0[3] = fmaf(hv.w, w0, a0[3]); a1[3] = fmaf(hv.w, w1, a1[3]);
        }
        __syncwarp();
#pragma unroll
        for (int s = 0; s < 4; s++) {
            hw[lane * 4 + s] = fmaxf(a0[s], 0.f);
            hw[(lane + 32) * 4 + s] = fmaxf(a1[s], 0.f);
        }
        __syncwarp();

#pragma unroll
        for (int s = 0; s < 4; s++) { a0[s] = b3A; a1[s] = b3B; }
#pragma unroll 8
        for (int k = 0; k < 64; k++) {
            float w0 = sW3[k * 64 + lane], w1 = sW3[k * 64 + lane + 32];
            float4 hv = *(float4*)&hw[k * 4];
            a0[0] = fmaf(hv.x, w0, a0[0]); a1[0] = fmaf(hv.x, w1, a1[0]);
            a0[1] = fmaf(hv.y, w0, a0[1]); a1[1] = fmaf(hv.y, w1, a1[1]);
            a0[2] = fmaf(hv.z, w0, a0[2]); a1[2] = fmaf(hv.z, w1, a1[2]);
            a0[3] = fmaf(hv.w, w0, a0[3]); a1[3] = fmaf(hv.w, w1, a1[3]);
        }
#pragma unroll
        for (int s = 0; s < 4; s++) {
            if (base + s < 625) {
                gA += fmaxf(a0[s], 0.f);
                gB += fmaxf(a1[s], 0.f);
            }
        }
        __syncwarp();
    }
    sGp[warp * 64 + lane] = gA;
    sGp[warp * 64 + lane + 32] = gB;
    __syncthreads();
    if (tid < 64) {
        float s = 0.f;
#pragma unroll
        for (int w = 0; w < 8; w++) s += sGp[w * 64 + tid];
        gout[(size_t)b * 64 + tid] = s;
    }
}

__global__ void final_head_kernel(const float* __restrict__ lat,
                                  const float* __restrict__ Wf1, const float* __restrict__ bf1,
                                  const float* __restrict__ Wf2, const float* __restrict__ bf2,
                                  const float* __restrict__ Wf3, const float* __restrict__ bf3,
                                  float* __restrict__ out) {
    __shared__ float sh1[8][64];
    int tid = threadIdx.x, lane = tid & 31, warp = tid >> 5;
    int b = blockIdx.x * 8 + warp;
    float a0 = bf1[lane], a1 = bf1[lane + 32];
    const float* g0 = d_g0 + (size_t)b * 64;
    const float* g1 = d_g1 + (size_t)b * 64;
    const float* lr = lat + (size_t)b * 256;
    for (int k = 0; k < 64; k++) {
        float g = g0[k];
        a0 = fmaf(g, Wf1[k * 64 + lane], a0);
        a1 = fmaf(g, Wf1[k * 64 + lane + 32], a1);
    }
    for (int k = 0; k < 64; k++) {
        float g = g1[k];
        a0 = fmaf(g, Wf1[(64 + k) * 64 + lane], a0);
        a1 = fmaf(g, Wf1[(64 + k) * 64 + lane + 32], a1);
    }
    for (int k = 0; k < 256; k++) {
        float g = lr[k];
        a0 = fmaf(g, Wf1[(128 + k) * 64 + lane], a0);
        a1 = fmaf(g, Wf1[(128 + k) * 64 + lane + 32], a1);
    }
    sh1[warp][lane] = fmaxf(a0, 0.f);
    sh1[warp][lane + 32] = fmaxf(a1, 0.f);
    __syncwarp();
    float c = bf2[lane];
    for (int k = 0; k < 64; k++) c = fmaf(sh1[warp][k], Wf2[k * 32 + lane], c);
    c = fmaxf(c, 0.f);
    float v = c * Wf3[lane];
#pragma unroll
    for (int o = 16; o; o >>= 1) v += __shfl_down_sync(0xffffffffu, v, o);
    if (lane == 0) out[b] = v + bf3[0];
}

extern "C" void kernel_launch(void* const* d_in, const int* in_sizes, int n_in,
                              void* d_out, int out_size) {
    const float* x0 = (const float*)d_in[0];
    const float* x1 = (const float*)d_in[1];
    const float* lat = (const float*)d_in[2];
    const float* Wc1 = (const float*)d_in[3];
    const float* Wc2 = (const float*)d_in[4];
    const float* Wc3 = (const float*)d_in[5];
    const float* Wc4 = (const float*)d_in[6];
    const float* bng = (const float*)d_in[7];
    const float* bnb = (const float*)d_in[8];
    const float* Wg1 = (const float*)d_in[9];
    const float* bg1 = (const float*)d_in[10];
    const float* Wg2 = (const float*)d_in[11];
    const float* bg2 = (const float*)d_in[12];
    const float* Wg3 = (const float*)d_in[13];
    const float* bg3 = (const float*)d_in[14];
    const float* Wf1 = (const float*)d_in[15];
    const float* bf1 = (const float*)d_in[16];
    const float* Wf2 = (const float*)d_in[17];
    const float* bf2 = (const float*)d_in[18];
    const float* Wf3 = (const float*)d_in[19];
    const float* bf3 = (const float*)d_in[20];
    float* out = (float*)d_out;

    float *buf1, *buf2, *buf3, *buf4, *wt1, *statsA, *g0p, *g1p;
    uint4 *wf2, *wf3, *wf4;
    cudaGetSymbolAddress((void**)&buf1, d_buf1);
    cudaGetSymbolAddress((void**)&buf2, d_buf2);
    cudaGetSymbolAddress((void**)&buf3, d_buf3);
    cudaGetSymbolAddress((void**)&buf4, d_buf4);
    cudaGetSymbolAddress((void**)&wt1, d_Wt1);
    cudaGetSymbolAddress((void**)&wf2, d_Wf2);
    cudaGetSymbolAddress((void**)&wf3, d_Wf3);
    cudaGetSymbolAddress((void**)&wf4, d_Wf4);
    cudaGetSymbolAddress((void**)&statsA, d_statsA);
    cudaGetSymbolAddress((void**)&g0p, d_g0);
    cudaGetSymbolAddress((void**)&g1p, d_g1);

    const int REL_SMEM = 15668 * 4;
    cudaFuncSetAttribute(relation_kernel, cudaFuncAttributeMaxDynamicSharedMemorySize, REL_SMEM);
    const int MMA_SMEM = 2 * 4352 * 4;   // 34816 B
    cudaFuncSetAttribute(conv_mma3_kernel<25, 25, 23, 23, 1>,
                         cudaFuncAttributeMaxDynamicSharedMemorySize, MMA_SMEM);
    cudaFuncSetAttribute(conv_mma3_kernel<23, 23, 11, 11, 2>,
                         cudaFuncAttributeMaxDynamicSharedMemorySize, MMA_SMEM);
    cudaFuncSetAttribute(conv_mma3_kernel<11, 11, 5, 5, 2>,
                         cudaFuncAttributeMaxDynamicSharedMemorySize, MMA_SMEM);

    zero_misc_kernel<<<1, 1024>>>();
    prep_weights_kernel<<<36, 256>>>(Wc1, Wc2, Wc3, Wc4);
    att_sum_kernel<<<64, 512>>>(lat);

    for (int im = 0; im < 2; im++) {
        const float* x = im ? x1 : x0;
        float* gp = im ? g1p : g0p;
        float* sl = statsA + im * 4 * 128;

        conv1_kernel<<<10000, 256>>>(x, wt1, buf1, sl + 0 * 128);
        conv_mma3_kernel<25, 25, 23, 23, 1><<<4232, 256, MMA_SMEM>>>(
            buf1, wf2, buf2, sl + 0 * 128, bng + 0, bnb + 0, 1.f / 640000.f,
            sl + 1 * 128);
        conv_mma3_kernel<23, 23, 11, 11, 2><<<968, 256, MMA_SMEM>>>(
            buf2, wf3, buf3, sl + 1 * 128, bng + 64, bnb + 64, 1.f / 541696.f,
            sl + 2 * 128);
        conv_mma3_kernel<11, 11, 5, 5, 2><<<200, 256, MMA_SMEM>>>(
            buf3, wf4, buf4, sl + 2 * 128, bng + 128, bnb + 128, 1.f / 123904.f,
            sl + 3 * 128);
        relation_kernel<<<1024, 256, REL_SMEM>>>(
            buf4, lat, Wg1, bg1, Wg2, bg2, Wg3, bg3,
            sl + 3 * 128, bng + 192, bnb + 192, 1.f / 25600.f, im, gp);
    }
    final_head_kernel<<<128, 256>>>(lat, Wf1, bf1, Wf2, bf2, Wf3, bf3, out);
}

// round 14
// speedup vs baseline: 1.1700x; 1.0475x over previous
#include <cuda_runtime.h>
#include <cuda_bf16.h>
#include <math.h>
#include <stdint.h>

// ---------------------------------------------------------------------------
// RelationNetworks forward. B=1024, C=64, L=64, H=64, IMG=27.
// conv chain: 27 ->(s1) 25 ->(s1) 23 ->(s2) 11 ->(s2) 5
// Activations NHWC. conv2/3/4 via mma.sync m16n8k16 bf16, 2-term hi/lo split,
// 3-pass product (pass-outermost), fp32 accum, fused BN stats.
// conv1: SIMT 128x64 tile, 8x8 regs/thread, K=27 exact.
// ---------------------------------------------------------------------------

__device__ float d_buf1[1024 * 625 * 64];
__device__ float d_buf2[1024 * 529 * 64];
__device__ float d_buf3[1024 * 121 * 64];
__device__ float d_buf4[1024 * 25 * 64];
__device__ float d_Wt1[32 * 64];          // conv1 [k pad32][oc], k=(ky*3+kx)*3+ic
// fragment-major packed bf16 weights:
// idx = (ch*2+wn)*256 + nf*64 + step*32 + lane -> {b0h, b1h, b0l, b1l}
__device__ uint4 d_Wf2[9216];
__device__ uint4 d_Wf3[9216];
__device__ uint4 d_Wf4[9216];
__device__ float d_statsA[8 * 128];
__device__ float d_Ssum[2];
__device__ float d_g0[1024 * 64];
__device__ float d_g1[1024 * 64];

// ---------------------------- helpers --------------------------------------
__device__ __forceinline__ uint16_t f2bf(float x, float& lo) {
    __nv_bfloat16 h = __float2bfloat16_rn(x);
    lo = x - __bfloat162float(h);
    return *(uint16_t*)&h;
}

__device__ __forceinline__ void mma_bf16(float c[4], const uint32_t a[4],
                                         uint32_t b0, uint32_t b1) {
    asm volatile(
        "mma.sync.aligned.m16n8k16.row.col.f32.bf16.bf16.f32 "
        "{%0,%1,%2,%3}, {%4,%5,%6,%7}, {%8,%9}, {%0,%1,%2,%3};"
        : "+f"(c[0]), "+f"(c[1]), "+f"(c[2]), "+f"(c[3])
        : "r"(a[0]), "r"(a[1]), "r"(a[2]), "r"(a[3]), "r"(b0), "r"(b1));
}

// ---------------------------- small kernels --------------------------------
// weight prep + zeroing of stats/softmax accumulators (merged)
__global__ void prep_weights_kernel(const float* __restrict__ Wc1,
                                    const float* __restrict__ Wc2,
                                    const float* __restrict__ Wc3,
                                    const float* __restrict__ Wc4) {
    int i = blockIdx.x * blockDim.x + threadIdx.x;
    if (i < 1024) d_statsA[i] = 0.f;
    if (i < 2) d_Ssum[i] = 0.f;
    if (i < 32 * 64) {
        int k = i >> 6, oc = i & 63;
        d_Wt1[i] = (k < 27) ? Wc1[oc * 27 + (k % 3) * 9 + (k / 3)] : 0.f;
    }
    if (i < 9216) {
        int lane = i & 31;
        int step = (i >> 5) & 1;
        int nf = (i >> 6) & 3;
        int wn = (i >> 8) & 1;
        int ch = i >> 9;                       // 0..17
        int n = wn * 32 + nf * 8 + (lane >> 2);
        int lt = lane & 3;
        int kb = ch * 32 + step * 16;
        int ks[4] = {kb + 2 * lt, kb + 2 * lt + 1, kb + 2 * lt + 8, kb + 2 * lt + 9};
        const float* Ws[3] = {Wc2, Wc3, Wc4};
        uint4* Wd[3] = {d_Wf2, d_Wf3, d_Wf4};
#pragma unroll
        for (int L = 0; L < 3; L++) {
            uint16_t h[4];
            float lo[4];
#pragma unroll
            for (int e = 0; e < 4; e++) {
                int k = ks[e];
                float v = Ws[L][n * 576 + (k & 63) * 9 + (k >> 6)];
                h[e] = f2bf(v, lo[e]);
            }
            uint16_t l0 = f2bf(lo[0], lo[0]), l1 = f2bf(lo[1], lo[1]);
            uint16_t l2 = f2bf(lo[2], lo[2]), l3 = f2bf(lo[3], lo[3]);
            Wd[L][i] = make_uint4(((uint32_t)h[1] << 16) | h[0],
                                  ((uint32_t)h[3] << 16) | h[2],
                                  ((uint32_t)l1 << 16) | l0,
                                  ((uint32_t)l3 << 16) | l2);
        }
    }
}

__global__ void att_sum_kernel(const float* __restrict__ lat) {
    int i = blockIdx.x * blockDim.x + threadIdx.x;
    float p0 = 0.f, p1 = 0.f;
    for (int idx = i; idx < 65536; idx += gridDim.x * blockDim.x) {
        int b = idx >> 6, c = idx & 63;
        p0 += expf(lat[(b * 4 + 2) * 64 + c]);
        p1 += expf(lat[(b * 4 + 3) * 64 + c]);
    }
#pragma unroll
    for (int o = 16; o; o >>= 1) {
        p0 += __shfl_down_sync(0xffffffffu, p0, o);
        p1 += __shfl_down_sync(0xffffffffu, p1, o);
    }
    if ((threadIdx.x & 31) == 0) {
        atomicAdd(&d_Ssum[0], p0);
        atomicAdd(&d_Ssum[1], p1);
    }
}

// ---- conv1 v2: NCHW input (3 ch), NHWC raw output, 128x64 tile, 8x8 regs --
__global__ void __launch_bounds__(128) conv1_kernel(
    const float* __restrict__ in, const float* __restrict__ Wt,
    float* __restrict__ out, float* __restrict__ slot) {
    __shared__ float As[27][136];
    __shared__ float Bs[27][64];
    __shared__ float sred[2][64][8];

    const int tid = threadIdx.x;
    const int lane = tid & 31, warp = tid >> 5;
    const int tx = tid & 7, ty = tid >> 3;
    const int m0 = blockIdx.x * 128;

    const int mg = m0 + tid;
    const int bI = mg / 625;
    const int sp = mg - bI * 625;
    const int oy = sp / 25;
    const int ox = sp - oy * 25;
    const float* inb = in + ((size_t)bI * 3) * 729 + oy * 27 + ox;

    // B: 27 x 64 floats
    for (int u = tid; u < 432; u += 128) {
        int ki = u >> 4, oc = (u & 15) * 4;
        *(float4*)&Bs[ki][oc] = *(const float4*)(Wt + ki * 64 + oc);
    }
    // A: own row, 27 gathered values (indices fold at compile time)
#pragma unroll
    for (int k = 0; k < 27; k++) {
        int ic = k % 3, w = k / 3;
        int ky = w / 3, kx = w - ky * 3;
        As[k][tid] = inb[ic * 729 + ky * 27 + kx];
    }
    __syncthreads();

    float acc[8][8];
#pragma unroll
    for (int i = 0; i < 8; i++)
#pragma unroll
        for (int j = 0; j < 8; j++) acc[i][j] = 0.f;

#pragma unroll
    for (int kk = 0; kk < 27; kk++) {
        float4 a0 = *(float4*)&As[kk][ty * 8];
        float4 a1 = *(float4*)&As[kk][ty * 8 + 4];
        float4 b0 = *(float4*)&Bs[kk][tx * 8];
        float4 b1 = *(float4*)&Bs[kk][tx * 8 + 4];
        float av[8] = {a0.x, a0.y, a0.z, a0.w, a1.x, a1.y, a1.z, a1.w};
        float bw[8] = {b0.x, b0.y, b0.z, b0.w, b1.x, b1.y, b1.z, b1.w};
#pragma unroll
        for (int i = 0; i < 8; i++)
#pragma unroll
            for (int j = 0; j < 8; j++)
                acc[i][j] = fmaf(av[i], bw[j], acc[i][j]);
    }

    // stats: reduce 8 rows per thread, then across ty via shfl(8,16), smem, atomics
#pragma unroll
    for (int j = 0; j < 8; j++) {
        float s = 0.f, q = 0.f;
#pragma unroll
        for (int i = 0; i < 8; i++) {
            float v = acc[i][j];
            s += v;
            q += v * v;
        }
        s += __shfl_down_sync(0xffffffffu, s, 8);
        s += __shfl_down_sync(0xffffffffu, s, 16);
        q += __shfl_down_sync(0xffffffffu, q, 8);
        q += __shfl_down_sync(0xffffffffu, q, 16);
        if (lane < 8) {
            sred[0][lane * 8 + j][warp] = s;
            sred[1][lane * 8 + j][warp] = q;
        }
    }
    // NHWC stores
#pragma unroll
    for (int i = 0; i < 8; i++) {
        float* dst = out + (size_t)(m0 + ty * 8 + i) * 64 + tx * 8;
        *(float4*)dst = make_float4(acc[i][0], acc[i][1], acc[i][2], acc[i][3]);
        *(float4*)(dst + 4) = make_float4(acc[i][4], acc[i][5], acc[i][6], acc[i][7]);
    }
    __syncthreads();
    {
        int si = tid >> 6, col = tid & 63;
        float v = 0.f;
#pragma unroll
        for (int w = 0; w < 4; w++) v += sred[si][col][w] + sred[si][col][w + 4];
        atomicAdd(&slot[si * 64 + col], v);
    }
}

// ---- conv64 via mma.sync bf16 hi/lo (3-pass): BM=128, BN=64, BK=32 --------
// A smem as bf16x2 [k2 16][row pad136] per stage (hi then lo). Fused stats.
template <int IH, int IW, int OH, int OW, int STRIDE>
__global__ void __launch_bounds__(256) conv_mma3_kernel(
    const float* __restrict__ in, const uint4* __restrict__ Wf,
    float* __restrict__ out,
    const float* __restrict__ stats, const float* __restrict__ bn_g,
    const float* __restrict__ bn_b, float invN, float* __restrict__ slot) {
    constexpr int OSP = OH * OW;
    constexpr int STG = 4352;                 // u32 per stage (hi 2176 + lo 2176)
    extern __shared__ uint32_t smu[];
    __shared__ float sBn[128];
    __shared__ float sred[2][64][8];

    const int tid = threadIdx.x;
    const int lane = tid & 31, warp = tid >> 5;
    const int wm = warp & 3, wn = warp >> 2;
    const int lg = lane >> 2, lt = lane & 3;

    if (tid < 64) {
        float s = stats[tid], q = stats[64 + tid];
        float mean = s * invN;
        float var = q * invN - mean * mean;
        float sc = bn_g[tid] * rsqrtf(var + 1e-5f);
        sBn[tid] = sc;
        sBn[64 + tid] = bn_b[tid] - mean * sc;
    }

    const int row = tid >> 1;
    const int khalf = tid & 1;
    const int mg = blockIdx.x * 128 + row;
    const int bI = mg / OSP;
    const int sp = mg - bI * OSP;
    const int oy = sp / OW;
    const int ox = sp - oy * OW;
    const float* inb = in + (((size_t)bI * IH + oy * STRIDE) * IW + ox * STRIDE) * 64;

    float c[2][4][4];
#pragma unroll
    for (int m = 0; m < 2; m++)
#pragma unroll
        for (int n = 0; n < 4; n++)
#pragma unroll
            for (int e = 0; e < 4; e++) c[m][n][e] = 0.f;

    __syncthreads();

    auto fill = [&](int s, int ch) {
        const int w = ch >> 1;
        const int ic0 = (ch & 1) * 32;
        const int ky = w / 3, kx = w - ky * 3;
        uint32_t* aH = smu + s * STG;
        uint32_t* aL = aH + 2176;
        const float* src = inb + (ky * IW + kx) * 64 + ic0 + khalf * 16;
        float xs[16];
#pragma unroll
        for (int j = 0; j < 4; j++) {
            float4 v = *(const float4*)(src + j * 4);
            int icb = ic0 + khalf * 16 + j * 4;
            float4 sc = *(const float4*)&sBn[icb];
            float4 sh = *(const float4*)&sBn[64 + icb];
            xs[j * 4 + 0] = fmaxf(fmaf(v.x, sc.x, sh.x), 0.f);
            xs[j * 4 + 1] = fmaxf(fmaf(v.y, sc.y, sh.y), 0.f);
            xs[j * 4 + 2] = fmaxf(fmaf(v.z, sc.z, sh.z), 0.f);
            xs[j * 4 + 3] = fmaxf(fmaf(v.w, sc.w, sh.w), 0.f);
        }
#pragma unroll
        for (int jj = 0; jj < 8; jj++) {
            float r0, r1;
            uint16_t h0 = f2bf(xs[2 * jj], r0);
            uint16_t h1 = f2bf(xs[2 * jj + 1], r1);
            uint16_t l0 = f2bf(r0, r0);
            uint16_t l1 = f2bf(r1, r1);
            int k2g = khalf * 8 + jj;
            aH[k2g * 136 + row] = ((uint32_t)h1 << 16) | h0;
            aL[k2g * 136 + row] = ((uint32_t)l1 << 16) | l0;
        }
    };

    fill(0, 0);
    __syncthreads();

#pragma unroll 1
    for (int ch = 0; ch < 18; ch++) {
        if (ch + 1 < 18) fill((ch + 1) & 1, ch + 1);

        const uint32_t* aH = smu + (ch & 1) * STG;
        const uint32_t* aL = aH + 2176;
        const uint4* wp = Wf + (size_t)(ch * 2 + wn) * 256 + lane;
#pragma unroll
        for (int step = 0; step < 2; step++) {
            uint32_t ah[2][4], al[2][4];
#pragma unroll
            for (int m = 0; m < 2; m++) {
                int rf = wm * 32 + m * 16 + lg;
                int k2 = step * 8 + lt;
                ah[m][0] = aH[k2 * 136 + rf];
                ah[m][1] = aH[k2 * 136 + rf + 8];
                ah[m][2] = aH[(k2 + 4) * 136 + rf];
                ah[m][3] = aH[(k2 + 4) * 136 + rf + 8];
                al[m][0] = aL[k2 * 136 + rf];
                al[m][1] = aL[k2 * 136 + rf + 8];
                al[m][2] = aL[(k2 + 4) * 136 + rf];
                al[m][3] = aL[(k2 + 4) * 136 + rf + 8];
            }
            uint4 b[4];
#pragma unroll
            for (int nf = 0; nf < 4; nf++) b[nf] = wp[nf * 64 + step * 32];
#pragma unroll
            for (int nf = 0; nf < 4; nf++)
#pragma unroll
                for (int m = 0; m < 2; m++)
                    mma_bf16(c[m][nf], ah[m], b[nf].x, b[nf].y);   // hi*hi
#pragma unroll
            for (int nf = 0; nf < 4; nf++)
#pragma unroll
                for (int m = 0; m < 2; m++)
                    mma_bf16(c[m][nf], ah[m], b[nf].z, b[nf].w);   // hi*lo
#pragma unroll
            for (int nf = 0; nf < 4; nf++)
#pragma unroll
                for (int m = 0; m < 2; m++)
                    mma_bf16(c[m][nf], al[m], b[nf].x, b[nf].y);   // lo*hi
        }
        __syncthreads();
    }

#pragma unroll
    for (int nf = 0; nf < 4; nf++) {
#pragma unroll
        for (int e = 0; e < 2; e++) {
            float s = c[0][nf][e] + c[0][nf][e + 2] + c[1][nf][e] + c[1][nf][e + 2];
            float q = c[0][nf][e] * c[0][nf][e] + c[0][nf][e + 2] * c[0][nf][e + 2] +
                      c[1][nf][e] * c[1][nf][e] + c[1][nf][e + 2] * c[1][nf][e + 2];
#pragma unroll
            for (int o = 16; o >= 4; o >>= 1) {
                s += __shfl_down_sync(0xffffffffu, s, o);
                q += __shfl_down_sync(0xffffffffu, q, o);
            }
            if (lane < 4) {
                int col = wn * 32 + nf * 8 + lane * 2 + e;
                sred[0][col][warp] = s;
                sred[1][col][warp] = q;
            }
        }
    }

#pragma unroll
    for (int m = 0; m < 2; m++) {
        int r = blockIdx.x * 128 + wm * 32 + m * 16 + lg;
#pragma unroll
        for (int nf = 0; nf < 4; nf++) {
            int col = wn * 32 + nf * 8 + lt * 2;
            *(float2*)(out + (size_t)r * 64 + col) =
                make_float2(c[m][nf][0], c[m][nf][1]);
            *(float2*)(out + (size_t)(r + 8) * 64 + col) =
                make_float2(c[m][nf][2], c[m][nf][3]);
        }
    }
    __syncthreads();
    if (tid < 128) {
        int si = tid >> 6, col = tid & 63;
        int wbase = (col < 32) ? 0 : 4;
        float v = sred[si][col][wbase] + sred[si][col][wbase + 1] +
                  sred[si][col][wbase + 2] + sred[si][col][wbase + 3];
        atomicAdd(&slot[si * 64 + col], v);
    }
}

// ---- relation network: one block per batch element ------------------------
__global__ void __launch_bounds__(256) relation_kernel(
    const float* __restrict__ conv4, const float* __restrict__ lat,
    const float* __restrict__ Wg1, const float* __restrict__ bg1,
    const float* __restrict__ Wg2, const float* __restrict__ bg2,
    const float* __restrict__ Wg3, const float* __restrict__ bg3,
    const float* __restrict__ stats, const float* __restrict__ bn_g,
    const float* __restrict__ bn_b, float invN,
    int im, float* __restrict__ gout) {
    extern __shared__ float sm[];
    float* sW2 = sm;
    float* sW3 = sm + 4096;
    float* sTi = sm + 8192;
    float* sTj = sm + 9792;
    float* sCT = sm + 11392;
    float* sTw = sm + 13042;
    float* sH  = sm + 13108;
    float* sGp = sm + 15156;
    __shared__ float sBn[128];

    const int tid = threadIdx.x;
    const int b = blockIdx.x;
    const int lane = tid & 31, warp = tid >> 5;

    if (tid < 64) {
        float s = stats[tid], q = stats[64 + tid];
        float mean = s * invN;
        float var = q * invN - mean * mean;
        float sc = bn_g[tid] * rsqrtf(var + 1e-5f);
        sBn[tid] = sc;
        sBn[64 + tid] = bn_b[tid] - mean * sc;
    }
    for (int i = tid; i < 4096; i += 256) {
        sW2[i] = Wg2[i];
        sW3[i] = Wg3[i];
    }
    __syncthreads();

    const float invS = 1.f / (d_Ssum[im] + 1e-9f);
    const float* aRow = lat + ((size_t)b * 4 + 2 + im) * 64;
    const float* wRow = lat + ((size_t)b * 4 + im) * 64;

    for (int i = tid; i < 1600; i += 256) {
        int p = i >> 6, cc = i & 63;
        float v = conv4[((size_t)b * 25 + p) * 64 + cc];
        v = fmaxf(fmaf(v, sBn[cc], sBn[64 + cc]), 0.f);
        v *= expf(aRow[cc]) * invS;
        sCT[p * 66 + cc] = v;
    }
    if (tid < 50) {
        int p = tid % 25, cc = tid / 25;
        sCT[p * 66 + 64 + cc] = (cc == 0) ? (float)(p % 5) - 2.f : (float)(p / 5) - 2.f;
    }
    if (tid < 64) {
        float acc = bg1[tid];
        for (int cc = 0; cc < 64; cc++)
            acc = fmaf(wRow[cc], Wg1[(132 + cc) * 64 + tid], acc);
        sTw[tid] = acc;
    }
    __syncthreads();

    for (int o = tid; o < 1600; o += 256) {
        int p = o >> 6, h = o & 63;
        float aj = 0.f, ai = 0.f;
        for (int cc = 0; cc < 66; cc++) {
            float ctv = sCT[p * 66 + cc];
            aj = fmaf(ctv, Wg1[cc * 64 + h], aj);
            ai = fmaf(ctv, Wg1[(66 + cc) * 64 + h], ai);
        }
        sTj[p * 64 + h] = aj;
        sTi[p * 64 + h] = ai;
    }
    __syncthreads();

    const float twA = sTw[lane], twB = sTw[lane + 32];
    const float b2A = bg2[lane], b2B = bg2[lane + 32];
    const float b3A = bg3[lane], b3B = bg3[lane + 32];
    float gA = 0.f, gB = 0.f;
    float* hw = sH + warp * 256;

    for (int it = 0; it < 20; it++) {
        const int base = it * 32 + warp * 4;
#pragma unroll
        for (int s = 0; s < 4; s++) {
            int pr = base + s;
            bool vld = pr < 625;
            int p = vld ? pr / 25 : 0, qq = vld ? pr % 25 : 0;
            hw[lane * 4 + s] = fmaxf(sTi[p * 64 + lane] + sTj[qq * 64 + lane] + twA, 0.f);
            hw[(lane + 32) * 4 + s] =
                fmaxf(sTi[p * 64 + lane + 32] + sTj[qq * 64 + lane + 32] + twB, 0.f);
        }
        __syncwarp();

        float a0[4], a1[4];
#pragma unroll
        for (int s = 0; s < 4; s++) { a0[s] = b2A; a1[s] = b2B; }
#pragma unroll 8
        for (int k = 0; k < 64; k++) {
            float w0 = sW2[k * 64 + lane], w1 = sW2[k * 64 + lane + 32];
            float4 hv = *(float4*)&hw[k * 4];
            a0[0] = fmaf(hv.x, w0, a0[0]); a1[0] = fmaf(hv.x, w1, a1[0]);
            a0[1] = fmaf(hv.y, w0, a0[1]); a1[1] = fmaf(hv.y, w1, a1[1]);
            a0[2] = fmaf(hv.z, w0, a0[2]); a1[2] = fmaf(hv.z, w1, a1[2]);
            a0[3] = fmaf(hv.w, w0, a0[3]); a1[3] = fmaf(hv.w, w1, a1[3]);
        }
        __syncwarp();
#pragma unroll
        for (int s = 0; s < 4; s++) {
            hw[lane * 4 + s] = fmaxf(a0[s], 0.f);
            hw[(lane + 32) * 4 + s] = fmaxf(a1[s], 0.f);
        }
        __syncwarp();

#pragma unroll
        for (int s = 0; s < 4; s++) { a0[s] = b3A; a1[s] = b3B; }
#pragma unroll 8
        for (int k = 0; k < 64; k++) {
            float w0 = sW3[k * 64 + lane], w1 = sW3[k * 64 + lane + 32];
            float4 hv = *(float4*)&hw[k * 4];
            a0[0] = fmaf(hv.x, w0, a0[0]); a1[0] = fmaf(hv.x, w1, a1[0]);
            a0[1] = fmaf(hv.y, w0, a0[1]); a1[1] = fmaf(hv.y, w1, a1[1]);
            a0[2] = fmaf(hv.z, w0, a0[2]); a1[2] = fmaf(hv.z, w1, a1[2]);
            a0[3] = fmaf(hv.w, w0, a0[3]); a1[3] = fmaf(hv.w, w1, a1[3]);
        }
#pragma unroll
        for (int s = 0; s < 4; s++) {
            if (base + s < 625) {
                gA += fmaxf(a0[s], 0.f);
                gB += fmaxf(a1[s], 0.f);
            }
        }
        __syncwarp();
    }
    sGp[warp * 64 + lane] = gA;
    sGp[warp * 64 + lane + 32] = gB;
    __syncthreads();
    if (tid < 64) {
        float s = 0.f;
#pragma unroll
        for (int w = 0; w < 8; w++) s += sGp[w * 64 + tid];
        gout[(size_t)b * 64 + tid] = s;
    }
}

__global__ void final_head_kernel(const float* __restrict__ lat,
                                  const float* __restrict__ Wf1, const float* __restrict__ bf1,
                                  const float* __restrict__ Wf2, const float* __restrict__ bf2,
                                  const float* __restrict__ Wf3, const float* __restrict__ bf3,
                                  float* __restrict__ out) {
    __shared__ float sh1[8][64];
    int tid = threadIdx.x, lane = tid & 31, warp = tid >> 5;
    int b = blockIdx.x * 8 + warp;
    float a0 = bf1[lane], a1 = bf1[lane + 32];
    const float* g0 = d_g0 + (size_t)b * 64;
    const float* g1 = d_g1 + (size_t)b * 64;
    const float* lr = lat + (size_t)b * 256;
    for (int k = 0; k < 64; k++) {
        float g = g0[k];
        a0 = fmaf(g, Wf1[k * 64 + lane], a0);
        a1 = fmaf(g, Wf1[k * 64 + lane + 32], a1);
    }
    for (int k = 0; k < 64; k++) {
        float g = g1[k];
        a0 = fmaf(g, Wf1[(64 + k) * 64 + lane], a0);
        a1 = fmaf(g, Wf1[(64 + k) * 64 + lane + 32], a1);
    }
    for (int k = 0; k < 256; k++) {
        float g = lr[k];
        a0 = fmaf(g, Wf1[(128 + k) * 64 + lane], a0);
        a1 = fmaf(g, Wf1[(128 + k) * 64 + lane + 32], a1);
    }
    sh1[warp][lane] = fmaxf(a0, 0.f);
    sh1[warp][lane + 32] = fmaxf(a1, 0.f);
    __syncwarp();
    float c = bf2[lane];
    for (int k = 0; k < 64; k++) c = fmaf(sh1[warp][k], Wf2[k * 32 + lane], c);
    c = fmaxf(c, 0.f);
    float v = c * Wf3[lane];
#pragma unroll
    for (int o = 16; o; o >>= 1) v += __shfl_down_sync(0xffffffffu, v, o);
    if (lane == 0) out[b] = v + bf3[0];
}

extern "C" void kernel_launch(void* const* d_in, const int* in_sizes, int n_in,
                              void* d_out, int out_size) {
    const float* x0 = (const float*)d_in[0];
    const float* x1 = (const float*)d_in[1];
    const float* lat = (const float*)d_in[2];
    const float* Wc1 = (const float*)d_in[3];
    const float* Wc2 = (const float*)d_in[4];
    const float* Wc3 = (const float*)d_in[5];
    const float* Wc4 = (const float*)d_in[6];
    const float* bng = (const float*)d_in[7];
    const float* bnb = (const float*)d_in[8];
    const float* Wg1 = (const float*)d_in[9];
    const float* bg1 = (const float*)d_in[10];
    const float* Wg2 = (const float*)d_in[11];
    const float* bg2 = (const float*)d_in[12];
    const float* Wg3 = (const float*)d_in[13];
    const float* bg3 = (const float*)d_in[14];
    const float* Wf1 = (const float*)d_in[15];
    const float* bf1 = (const float*)d_in[16];
    const float* Wf2 = (const float*)d_in[17];
    const float* bf2 = (const float*)d_in[18];
    const float* Wf3 = (const float*)d_in[19];
    const float* bf3 = (const float*)d_in[20];
    float* out = (float*)d_out;

    float *buf1, *buf2, *buf3, *buf4, *wt1, *statsA, *g0p, *g1p;
    uint4 *wf2, *wf3, *wf4;
    cudaGetSymbolAddress((void**)&buf1, d_buf1);
    cudaGetSymbolAddress((void**)&buf2, d_buf2);
    cudaGetSymbolAddress((void**)&buf3, d_buf3);
    cudaGetSymbolAddress((void**)&buf4, d_buf4);
    cudaGetSymbolAddress((void**)&wt1, d_Wt1);
    cudaGetSymbolAddress((void**)&wf2, d_Wf2);
    cudaGetSymbolAddress((void**)&wf3, d_Wf3);
    cudaGetSymbolAddress((void**)&wf4, d_Wf4);
    cudaGetSymbolAddress((void**)&statsA, d_statsA);
    cudaGetSymbolAddress((void**)&g0p, d_g0);
    cudaGetSymbolAddress((void**)&g1p, d_g1);

    const int REL_SMEM = 15668 * 4;
    cudaFuncSetAttribute(relation_kernel, cudaFuncAttributeMaxDynamicSharedMemorySize, REL_SMEM);
    const int MMA_SMEM = 2 * 4352 * 4;   // 34816 B
    cudaFuncSetAttribute(conv_mma3_kernel<25, 25, 23, 23, 1>,
                         cudaFuncAttributeMaxDynamicSharedMemorySize, MMA_SMEM);
    cudaFuncSetAttribute(conv_mma3_kernel<23, 23, 11, 11, 2>,
                         cudaFuncAttributeMaxDynamicSharedMemorySize, MMA_SMEM);
    cudaFuncSetAttribute(conv_mma3_kernel<11, 11, 5, 5, 2>,
                         cudaFuncAttributeMaxDynamicSharedMemorySize, MMA_SMEM);

    prep_weights_kernel<<<36, 256>>>(Wc1, Wc2, Wc3, Wc4);
    att_sum_kernel<<<64, 512>>>(lat);

    for (int im = 0; im < 2; im++) {
        const float* x = im ? x1 : x0;
        float* gp = im ? g1p : g0p;
        float* sl = statsA + im * 4 * 128;

        conv1_kernel<<<5000, 128>>>(x, wt1, buf1, sl + 0 * 128);
        conv_mma3_kernel<25, 25, 23, 23, 1><<<4232, 256, MMA_SMEM>>>(
            buf1, wf2, buf2, sl + 0 * 128, bng + 0, bnb + 0, 1.f / 640000.f,
            sl + 1 * 128);
        conv_mma3_kernel<23, 23, 11, 11, 2><<<968, 256, MMA_SMEM>>>(
            buf2, wf3, buf3, sl + 1 * 128, bng + 64, bnb + 64, 1.f / 541696.f,
            sl + 2 * 128);
        conv_mma3_kernel<11, 11, 5, 5, 2><<<200, 256, MMA_SMEM>>>(
            buf3, wf4, buf4, sl + 2 * 128, bng + 128, bnb + 128, 1.f / 123904.f,
            sl + 3 * 128);
        relation_kernel<<<1024, 256, REL_SMEM>>>(
            buf4, lat, Wg1, bg1, Wg2, bg2, Wg3, bg3,
            sl + 3 * 128, bng + 192, bnb + 192, 1.f / 25600.f, im, gp);
    }
    final_head_kernel<<<128, 256>>>(lat, Wf1, bf1, Wf2, bf2, Wf3, bf3, out);
}